// round 1
// baseline (speedup 1.0000x reference)
#include <cuda_runtime.h>

// Problem constants (fixed shapes)
#define D_MODEL 1024
#define RANK    256
#define R2      (2*RANK)     // 512
#define BATCH   4
#define SEQ     2048
#define MTOT    (BATCH*SEQ)  // 8192
#define TCH     128
#define NCH     (SEQ/TCH)    // 16

// ---------------- scratch (device globals; no cudaMalloc allowed) ------------
__device__ float g_Q  [MTOT*D_MODEL];
__device__ float g_Km [MTOT*D_MODEL];
__device__ float g_Z  [MTOT*D_MODEL];
__device__ float g_P  [MTOT*D_MODEL];
__device__ float g_A2 [MTOT*R2];
__device__ float g_C2 [MTOT*R2];
__device__ float g_G  [MTOT*R2];
__device__ float g_zt [MTOT*RANK];
__device__ float g_Vc [D_MODEL*R2];
__device__ float g_Wc [D_MODEL*R2];
__device__ float g_Uc [D_MODEL*R2];
__device__ float g_bv [D_MODEL];
__device__ float g_cs [BATCH*NCH*D_MODEL];

// ---------------- GEMM: C[M,N] = A[M,K] * B ---------------------------------
// B_NT=true : B stored [N,K] row-major (nn.Linear weight, x @ W.T)
// B_NT=false: B stored [K,N] row-major
#define BM 128
#define BN 128
#define BK 16

template<bool B_NT, bool BIAS>
__global__ __launch_bounds__(256, 2)
void gemm_kernel(const float* __restrict__ A, const float* __restrict__ B,
                 float* __restrict__ C, int N, int K,
                 const float* __restrict__ bias)
{
    __shared__ float As[2][BK][BM];
    __shared__ float Bs[2][BK][BN];

    const int tid = threadIdx.x;
    const int bm  = blockIdx.y * BM;
    const int bn  = blockIdx.x * BN;

    const int a_row = tid >> 2;          // 0..63
    const int a_c4  = (tid & 3) << 2;    // 0,4,8,12
    const int b_kr  = tid >> 5;          // 0..7  (NN path)
    const int b_c4  = (tid & 31) << 2;   // 0..124

    float4 ar0, ar1, br0, br1;

    auto gload = [&](int kt) {
        const float* ap = A + (long)(bm + a_row) * K + kt * BK + a_c4;
        ar0 = *(const float4*)ap;
        ar1 = *(const float4*)(ap + 64L * K);
        if (B_NT) {
            const float* bp = B + (long)(bn + a_row) * K + kt * BK + a_c4;
            br0 = *(const float4*)bp;
            br1 = *(const float4*)(bp + 64L * K);
        } else {
            const float* bp = B + ((long)kt * BK + b_kr) * N + bn + b_c4;
            br0 = *(const float4*)bp;
            br1 = *(const float4*)(bp + 8L * N);
        }
    };
    auto sstore = [&](int buf) {
        As[buf][a_c4+0][a_row]    = ar0.x;
        As[buf][a_c4+1][a_row]    = ar0.y;
        As[buf][a_c4+2][a_row]    = ar0.z;
        As[buf][a_c4+3][a_row]    = ar0.w;
        As[buf][a_c4+0][a_row+64] = ar1.x;
        As[buf][a_c4+1][a_row+64] = ar1.y;
        As[buf][a_c4+2][a_row+64] = ar1.z;
        As[buf][a_c4+3][a_row+64] = ar1.w;
        if (B_NT) {
            Bs[buf][a_c4+0][a_row]    = br0.x;
            Bs[buf][a_c4+1][a_row]    = br0.y;
            Bs[buf][a_c4+2][a_row]    = br0.z;
            Bs[buf][a_c4+3][a_row]    = br0.w;
            Bs[buf][a_c4+0][a_row+64] = br1.x;
            Bs[buf][a_c4+1][a_row+64] = br1.y;
            Bs[buf][a_c4+2][a_row+64] = br1.z;
            Bs[buf][a_c4+3][a_row+64] = br1.w;
        } else {
            *(float4*)&Bs[buf][b_kr  ][b_c4] = br0;
            *(float4*)&Bs[buf][b_kr+8][b_c4] = br1;
        }
    };

    float acc[8][8];
    #pragma unroll
    for (int i = 0; i < 8; i++)
        #pragma unroll
        for (int j = 0; j < 8; j++) acc[i][j] = 0.f;

    gload(0);
    sstore(0);
    __syncthreads();

    const int ty = tid >> 4;   // 0..15
    const int tx = tid & 15;   // 0..15
    const int nk = K / BK;

    for (int kt = 0; kt < nk; kt++) {
        const int cur = kt & 1;
        const bool pref = (kt + 1 < nk);
        if (pref) gload(kt + 1);

        #pragma unroll
        for (int kk = 0; kk < BK; kk++) {
            float av[8], bv_[8];
            *(float4*)&av[0]  = *(const float4*)&As[cur][kk][ty*4];
            *(float4*)&av[4]  = *(const float4*)&As[cur][kk][ty*4+64];
            *(float4*)&bv_[0] = *(const float4*)&Bs[cur][kk][tx*4];
            *(float4*)&bv_[4] = *(const float4*)&Bs[cur][kk][tx*4+64];
            #pragma unroll
            for (int i = 0; i < 8; i++)
                #pragma unroll
                for (int j = 0; j < 8; j++)
                    acc[i][j] = fmaf(av[i], bv_[j], acc[i][j]);
        }
        if (pref) sstore(cur ^ 1);
        __syncthreads();
    }

    #pragma unroll
    for (int i = 0; i < 8; i++) {
        const int row = bm + (i < 4 ? ty*4 + i : 64 + ty*4 + (i - 4));
        float* cp = C + (long)row * N + bn;
        #pragma unroll
        for (int jh = 0; jh < 2; jh++) {
            const int coff = jh ? tx*4 + 64 : tx*4;
            float4 v;
            v.x = acc[i][jh*4+0];
            v.y = acc[i][jh*4+1];
            v.z = acc[i][jh*4+2];
            v.w = acc[i][jh*4+3];
            if (BIAS) {
                v.x += bias[bn + coff + 0];
                v.y += bias[bn + coff + 1];
                v.z += bias[bn + coff + 2];
                v.w += bias[bn + coff + 3];
            }
            *(float4*)(cp + coff) = v;
        }
    }
}

// ---------------- causal cumulative sum (3-pass chunked scan) ---------------
__global__ void scan_partial(const float* __restrict__ Y, float* __restrict__ O,
                             float* __restrict__ cs, int C)
{
    const int col = blockIdx.x * 128 + threadIdx.x;
    const int ch  = blockIdx.y;
    const int b   = blockIdx.z;
    const long base = ((long)b * SEQ + (long)ch * TCH) * C + col;
    float run = 0.f;
    for (int t = 0; t < TCH; t++) {
        run += Y[base + (long)t * C];
        O[base + (long)t * C] = run;
    }
    cs[((long)b * NCH + ch) * C + col] = run;
}

__global__ void scan_offsets(float* __restrict__ cs, int C)
{
    const int i = blockIdx.x * blockDim.x + threadIdx.x;
    if (i >= BATCH * C) return;
    const int b = i / C, col = i % C;
    float off = 0.f;
    for (int ch = 0; ch < NCH; ch++) {
        const long idx = ((long)b * NCH + ch) * C + col;
        const float v = cs[idx];
        cs[idx] = off;
        off += v;
    }
}

template<bool DIVIDE>
__global__ void scan_apply(float* __restrict__ O, const float* __restrict__ cs, int C)
{
    const long total = (long)MTOT * C;
    for (long i = (long)blockIdx.x * blockDim.x + threadIdx.x; i < total;
         i += (long)gridDim.x * blockDim.x) {
        const int  c  = (int)(i % C);
        const long mt = i / C;
        const int  t  = (int)(mt % SEQ);
        const int  b  = (int)(mt / SEQ);
        const int  ch = t / TCH;
        float v = O[i] + cs[((long)b * NCH + ch) * C + c];
        if (DIVIDE) v *= 1.0f / (float)(t + 1);
        O[i] = v;
    }
}

// ---------------- elementwise glue ------------------------------------------
// G[:, :R]  = a_b * c_b / cnt
// G[:, R:]  = alpha * a_t * z_t * c_t / cnt
__global__ void build_g(const float* __restrict__ A2, const float* __restrict__ C2,
                        const float* __restrict__ zt, const float* __restrict__ alpha,
                        float* __restrict__ G)
{
    const int i = blockIdx.x * blockDim.x + threadIdx.x; // MTOT*RANK = 2M
    if (i >= MTOT * RANK) return;
    const int m = i / RANK, r = i % RANK;
    const float inv = 1.0f / (float)((m % SEQ) + 1);
    const long o = (long)m * R2 + r;
    const float gb = A2[o] * C2[o] * inv;
    const float gt = alpha[0] * A2[o + RANK] * zt[(long)m * RANK + r] * C2[o + RANK] * inv;
    G[o]        = gb;
    G[o + RANK] = gt;
}

// O[d, 0:R] = A[d,:]; O[d, R:2R] = B[d,:]
__global__ void concat2(const float* __restrict__ A, const float* __restrict__ B,
                        float* __restrict__ O)
{
    const int i = blockIdx.x * blockDim.x + threadIdx.x;
    if (i >= D_MODEL * R2) return;
    const int d = i / R2, c = i % R2;
    O[i] = (c < RANK) ? A[d * RANK + c] : B[d * RANK + (c - RANK)];
}

__global__ void biasvec_k(const float* __restrict__ bb, const float* __restrict__ bt,
                          const float* __restrict__ alpha, float* __restrict__ bv)
{
    const int i = blockIdx.x * blockDim.x + threadIdx.x;
    if (i < D_MODEL) bv[i] = bb[i] + alpha[0] * bt[i];
}

// ---------------- launch ------------------------------------------------------
extern "C" void kernel_launch(void* const* d_in, const int* in_sizes, int n_in,
                              void* d_out, int out_size)
{
    const float* x      = (const float*)d_in[0];
    const float* Wq     = (const float*)d_in[1];
    const float* Wk     = (const float*)d_in[2];
    const float* Wo     = (const float*)d_in[3];
    const float* U_b    = (const float*)d_in[4];
    const float* V_b    = (const float*)d_in[5];
    const float* W_b    = (const float*)d_in[6];
    const float* bias_b = (const float*)d_in[7];
    const float* U_t    = (const float*)d_in[8];
    const float* V_t    = (const float*)d_in[9];
    const float* W_t    = (const float*)d_in[10];
    const float* X_t    = (const float*)d_in[11];
    const float* bias_t = (const float*)d_in[12];
    const float* alpha  = (const float*)d_in[13];
    float* out = (float*)d_out;

    float *Q, *Km, *Z, *P, *A2, *C2, *G, *zt, *Vc, *Wc, *Uc, *bv, *cs;
    cudaGetSymbolAddress((void**)&Q,  g_Q);
    cudaGetSymbolAddress((void**)&Km, g_Km);
    cudaGetSymbolAddress((void**)&Z,  g_Z);
    cudaGetSymbolAddress((void**)&P,  g_P);
    cudaGetSymbolAddress((void**)&A2, g_A2);
    cudaGetSymbolAddress((void**)&C2, g_C2);
    cudaGetSymbolAddress((void**)&G,  g_G);
    cudaGetSymbolAddress((void**)&zt, g_zt);
    cudaGetSymbolAddress((void**)&Vc, g_Vc);
    cudaGetSymbolAddress((void**)&Wc, g_Wc);
    cudaGetSymbolAddress((void**)&Uc, g_Uc);
    cudaGetSymbolAddress((void**)&bv, g_bv);
    cudaGetSymbolAddress((void**)&cs, g_cs);

    // weight concatenations + bias vector
    const int nc = (D_MODEL * R2 + 255) / 256;
    concat2<<<nc, 256>>>(V_b, V_t, Vc);
    concat2<<<nc, 256>>>(W_b, W_t, Wc);
    concat2<<<nc, 256>>>(U_b, U_t, Uc);
    biasvec_k<<<4, 256>>>(bias_b, bias_t, alpha, bv);

    // Q = x @ Wq.T ; K = x @ Wk.T
    dim3 gQK(D_MODEL / BN, MTOT / BM);
    gemm_kernel<true,  false><<<gQK, 256>>>(x, Wq, Q,  D_MODEL, D_MODEL, nullptr);
    gemm_kernel<true,  false><<<gQK, 256>>>(x, Wk, Km, D_MODEL, D_MODEL, nullptr);

    // Z = cumsum(x, axis=T) / counts
    dim3 gsx(D_MODEL / 128, NCH, BATCH);
    scan_partial<<<gsx, 128>>>(x, Z, cs, D_MODEL);
    scan_offsets<<<(BATCH * D_MODEL + 255) / 256, 256>>>(cs, D_MODEL);
    scan_apply<true><<<4096, 256>>>(Z, cs, D_MODEL);

    // A2 = Q @ [V_b|V_t] ; C2 = K @ [W_b|W_t] ; zt = Z @ X_t
    dim3 gA2(R2 / BN, MTOT / BM);
    gemm_kernel<false, false><<<gA2, 256>>>(Q,  Vc,  A2, R2,   D_MODEL, nullptr);
    gemm_kernel<false, false><<<gA2, 256>>>(Km, Wc,  C2, R2,   D_MODEL, nullptr);
    dim3 gZT(RANK / BN, MTOT / BM);
    gemm_kernel<false, false><<<gZT, 256>>>(Z,  X_t, zt, RANK, D_MODEL, nullptr);

    // causal cumsum over C2 (both halves), in place
    dim3 gsc(R2 / 128, NCH, BATCH);
    scan_partial<<<gsc, 128>>>(C2, C2, cs, R2);
    scan_offsets<<<(BATCH * R2 + 255) / 256, 256>>>(cs, R2);
    scan_apply<false><<<2048, 256>>>(C2, cs, R2);

    // G = [a_b*c_b/cnt | alpha*a_t*z_t*c_t/cnt]
    build_g<<<(MTOT * RANK + 255) / 256, 256>>>(A2, C2, zt, alpha, G);

    // P = G @ [U_b|U_t].T + (bias_b + alpha*bias_t) ; out = P @ Wo.T
    gemm_kernel<true, true ><<<gQK, 256>>>(G, Uc, P,   D_MODEL, R2,      bv);
    gemm_kernel<true, false><<<gQK, 256>>>(P, Wo, out, D_MODEL, D_MODEL, nullptr);
}

// round 3
// speedup vs baseline: 1.9709x; 1.9709x over previous
#include <cuda_runtime.h>
#include <cuda_bf16.h>
#include <cstdint>

// Problem constants (fixed shapes)
#define D_MODEL 1024
#define RANK    256
#define R2      (2*RANK)     // 512
#define BATCH   4
#define SEQ     2048
#define MTOT    (BATCH*SEQ)  // 8192
#define TCH     128
#define NCH     (SEQ/TCH)    // 16

// ---------------- scratch (device globals; no cudaMalloc allowed) ------------
__device__ float g_Q  [MTOT*D_MODEL];
__device__ float g_Km [MTOT*D_MODEL];
__device__ float g_Z  [MTOT*D_MODEL];
__device__ float g_P  [MTOT*D_MODEL];
__device__ float g_A2 [MTOT*R2];
__device__ float g_C2 [MTOT*R2];
__device__ float g_G  [MTOT*R2];
__device__ float g_zt [MTOT*RANK];
__device__ float g_VcT[R2*D_MODEL];
__device__ float g_WcT[R2*D_MODEL];
__device__ float g_XtT[RANK*D_MODEL];
__device__ float g_Uc [D_MODEL*R2];
__device__ float g_bv [D_MODEL];
__device__ float g_cs [BATCH*NCH*D_MODEL];

// ====================== mma.sync helpers =====================================
#define LDSM_X4(R, A) \
    asm volatile("ldmatrix.sync.aligned.m8n8.x4.shared.b16 {%0,%1,%2,%3}, [%4];" \
        : "=r"((R)[0]), "=r"((R)[1]), "=r"((R)[2]), "=r"((R)[3]) : "r"(A))
#define LDSM_X2(R, A) \
    asm volatile("ldmatrix.sync.aligned.m8n8.x2.shared.b16 {%0,%1}, [%2];" \
        : "=r"((R)[0]), "=r"((R)[1]) : "r"(A))
#define MMA_BF16(D, Ar, Br) \
    asm volatile("mma.sync.aligned.m16n8k16.row.col.f32.bf16.bf16.f32 " \
        "{%0,%1,%2,%3}, {%4,%5,%6,%7}, {%8,%9}, {%0,%1,%2,%3};" \
        : "+f"((D)[0]), "+f"((D)[1]), "+f"((D)[2]), "+f"((D)[3]) \
        : "r"((Ar)[0]), "r"((Ar)[1]), "r"((Ar)[2]), "r"((Ar)[3]), \
          "r"((Br)[0]), "r"((Br)[1]))

__device__ __forceinline__ uint32_t smem_u32(const void* p) {
    uint32_t a;
    asm("{ .reg .u64 t; cvta.to.shared.u64 t, %1; cvt.u32.u64 %0, t; }" : "=r"(a) : "l"(p));
    return a;
}

// paired-row swizzled byte offset for element chunk (m in [0,128), c in [0,4))
// physical: 128B rows hold two logical 64B rows; 16B chunk index XOR'd with p&7.
__device__ __forceinline__ uint32_t swoff(int m, int c) {
    const int p  = m >> 1;
    const int cc = (((m & 1) << 2) | c) ^ (p & 7);
    return (uint32_t)(p * 128 + cc * 16);
}

__device__ __forceinline__ uint32_t pack2(__nv_bfloat16 x, __nv_bfloat16 y) {
    return (uint32_t)__bfloat16_as_ushort(x) | ((uint32_t)__bfloat16_as_ushort(y) << 16);
}

// split 8 fp32 into hi/lo bf16 chunks and store (16B each)
__device__ __forceinline__ void split_sts(float4 v0, float4 v1, char* hp, char* lp) {
    float s[8] = {v0.x, v0.y, v0.z, v0.w, v1.x, v1.y, v1.z, v1.w};
    __nv_bfloat16 h[8], l[8];
#pragma unroll
    for (int q = 0; q < 8; q++) {
        h[q] = __float2bfloat16(s[q]);
        l[q] = __float2bfloat16(s[q] - __bfloat162float(h[q]));
    }
    uint4 H, L;
    H.x = pack2(h[0], h[1]); H.y = pack2(h[2], h[3]);
    H.z = pack2(h[4], h[5]); H.w = pack2(h[6], h[7]);
    L.x = pack2(l[0], l[1]); L.y = pack2(l[2], l[3]);
    L.z = pack2(l[4], l[5]); L.w = pack2(l[6], l[7]);
    *(uint4*)hp = H;
    *(uint4*)lp = L;
}

// ====================== 3xBF16-split tensor GEMM =============================
// C[M,N] = A[M,K] @ B[N,K]^T   (both K-major row-major). 128x128 CTA, BK=32.
// SMEM buffer: Ah(8K) Al(8K) Bh(8K) Bl(8K) = 32KB, double buffered = 64KB.
#define TILE_B   8192
#define BUF_B    32768
#define GEMM_SMEM 65536

template<bool BIAS>
__global__ __launch_bounds__(256, 1)
void gemm_bf3(const float* __restrict__ A, const float* __restrict__ B,
              float* __restrict__ C, int N, int K, const float* __restrict__ bias)
{
    extern __shared__ __align__(128) char sm[];
    const uint32_t sb = smem_u32(sm);
    const int tid  = threadIdx.x;
    const int wid  = tid >> 5, lane = tid & 31;
    const int warpM = wid & 1, warpN = wid >> 1;
    const long bm = (long)blockIdx.y * 128, bn = (long)blockIdx.x * 128;

    // ldmatrix source offsets (lane-dependent, swizzled)
    uint32_t offA[4][2], offB[4][2];
#pragma unroll
    for (int i = 0; i < 4; i++) {
        const int m = warpM * 64 + i * 16 + (lane & 15);
#pragma unroll
        for (int kg = 0; kg < 2; kg++)
            offA[i][kg] = swoff(m, 2 * kg + (lane >> 4));
    }
#pragma unroll
    for (int j = 0; j < 4; j++) {
        const int n = warpN * 32 + j * 8 + (lane & 7);
#pragma unroll
        for (int kg = 0; kg < 2; kg++)
            offB[j][kg] = swoff(n, 2 * kg + ((lane >> 3) & 1));
    }

    // global load / sts mapping: thread handles rows r0 and r0+64, chunk c0
    const int r0 = tid >> 2, c0 = tid & 3;
    const uint32_t so0 = swoff(r0, c0), so1 = swoff(r0 + 64, c0);
    const float* Ag0 = A + (bm + r0) * K + c0 * 8;
    const float* Ag1 = Ag0 + 64L * K;
    const float* Bg0 = B + (bn + r0) * K + c0 * 8;
    const float* Bg1 = Bg0 + 64L * K;

    float4 pa0, pa1, pa2, pa3, pb0, pb1, pb2, pb3;
    auto ldg = [&](int kt) {
        const long o = (long)kt * 32;
        pa0 = *(const float4*)(Ag0 + o); pa1 = *(const float4*)(Ag0 + o + 4);
        pa2 = *(const float4*)(Ag1 + o); pa3 = *(const float4*)(Ag1 + o + 4);
        pb0 = *(const float4*)(Bg0 + o); pb1 = *(const float4*)(Bg0 + o + 4);
        pb2 = *(const float4*)(Bg1 + o); pb3 = *(const float4*)(Bg1 + o + 4);
    };
    auto sts = [&](int buf) {
        char* base = sm + buf * BUF_B;
        split_sts(pa0, pa1, base + so0,              base + TILE_B + so0);
        split_sts(pa2, pa3, base + so1,              base + TILE_B + so1);
        split_sts(pb0, pb1, base + 2*TILE_B + so0,   base + 3*TILE_B + so0);
        split_sts(pb2, pb3, base + 2*TILE_B + so1,   base + 3*TILE_B + so1);
    };

    float acc[4][4][4];
#pragma unroll
    for (int i = 0; i < 4; i++)
#pragma unroll
        for (int j = 0; j < 4; j++)
#pragma unroll
            for (int q = 0; q < 4; q++) acc[i][j][q] = 0.f;

    const int nk = K / 32;
    ldg(0);
    sts(0);
    __syncthreads();

#pragma unroll 1
    for (int kt = 0; kt < nk; kt++) {
        const bool pref = (kt + 1 < nk);
        if (pref) ldg(kt + 1);

        const uint32_t bb = sb + (kt & 1) * BUF_B;
#pragma unroll
        for (int kg = 0; kg < 2; kg++) {
            uint32_t ah[4][4], al[4][4], bh[4][2], bl[4][2];
#pragma unroll
            for (int i = 0; i < 4; i++) {
                LDSM_X4(ah[i], bb + offA[i][kg]);
                LDSM_X4(al[i], bb + TILE_B + offA[i][kg]);
            }
#pragma unroll
            for (int j = 0; j < 4; j++) {
                LDSM_X2(bh[j], bb + 2*TILE_B + offB[j][kg]);
                LDSM_X2(bl[j], bb + 3*TILE_B + offB[j][kg]);
            }
#pragma unroll
            for (int i = 0; i < 4; i++)
#pragma unroll
                for (int j = 0; j < 4; j++) {
                    MMA_BF16(acc[i][j], ah[i], bh[j]);
                    MMA_BF16(acc[i][j], ah[i], bl[j]);
                    MMA_BF16(acc[i][j], al[i], bh[j]);
                }
        }
        if (pref) sts((kt + 1) & 1);
        __syncthreads();
    }

    // epilogue
    const int g = lane >> 2, tg = lane & 3;
#pragma unroll
    for (int i = 0; i < 4; i++) {
        const long row = bm + warpM * 64 + i * 16 + g;
#pragma unroll
        for (int j = 0; j < 4; j++) {
            const int col = (int)bn + warpN * 32 + j * 8 + 2 * tg;
            float b0 = 0.f, b1 = 0.f;
            if (BIAS) { b0 = bias[col]; b1 = bias[col + 1]; }
            float2 v0 = make_float2(acc[i][j][0] + b0, acc[i][j][1] + b1);
            float2 v1 = make_float2(acc[i][j][2] + b0, acc[i][j][3] + b1);
            *(float2*)(C + row * N + col)       = v0;
            *(float2*)(C + (row + 8) * N + col) = v1;
        }
    }
}

// ---------------- causal cumulative sum (3-pass chunked scan) ---------------
__global__ void scan_partial(const float* __restrict__ Y, float* __restrict__ O,
                             float* __restrict__ cs, int C)
{
    const int col = blockIdx.x * 128 + threadIdx.x;
    const int ch  = blockIdx.y;
    const int b   = blockIdx.z;
    const long base = ((long)b * SEQ + (long)ch * TCH) * C + col;
    float run = 0.f;
    for (int t = 0; t < TCH; t++) {
        run += Y[base + (long)t * C];
        O[base + (long)t * C] = run;
    }
    cs[((long)b * NCH + ch) * C + col] = run;
}

__global__ void scan_offsets(float* __restrict__ cs, int C)
{
    const int i = blockIdx.x * blockDim.x + threadIdx.x;
    if (i >= BATCH * C) return;
    const int b = i / C, col = i % C;
    float off = 0.f;
    for (int ch = 0; ch < NCH; ch++) {
        const long idx = ((long)b * NCH + ch) * C + col;
        const float v = cs[idx];
        cs[idx] = off;
        off += v;
    }
}

template<bool DIVIDE>
__global__ void scan_apply(float* __restrict__ O, const float* __restrict__ cs, int C)
{
    const long total = (long)MTOT * C;
    for (long i = (long)blockIdx.x * blockDim.x + threadIdx.x; i < total;
         i += (long)gridDim.x * blockDim.x) {
        const int  c  = (int)(i % C);
        const long mt = i / C;
        const int  t  = (int)(mt % SEQ);
        const int  b  = (int)(mt / SEQ);
        const int  ch = t / TCH;
        float v = O[i] + cs[((long)b * NCH + ch) * C + c];
        if (DIVIDE) v *= 1.0f / (float)(t + 1);
        O[i] = v;
    }
}

// ---------------- elementwise glue ------------------------------------------
__global__ void build_g(const float* __restrict__ A2, const float* __restrict__ C2,
                        const float* __restrict__ zt, const float* __restrict__ alpha,
                        float* __restrict__ G)
{
    const int i = blockIdx.x * blockDim.x + threadIdx.x;
    if (i >= MTOT * RANK) return;
    const int m = i / RANK, r = i % RANK;
    const float inv = 1.0f / (float)((m % SEQ) + 1);
    const long o = (long)m * R2 + r;
    const float gb = A2[o] * C2[o] * inv;
    const float gt = alpha[0] * A2[o + RANK] * zt[(long)m * RANK + r] * C2[o + RANK] * inv;
    G[o]        = gb;
    G[o + RANK] = gt;
}

// Uc[d, c] = c<R ? U_b[d,c] : U_t[d,c-R]   (shape [D, R2])
__global__ void concat2(const float* __restrict__ A, const float* __restrict__ B,
                        float* __restrict__ O)
{
    const int i = blockIdx.x * blockDim.x + threadIdx.x;
    if (i >= D_MODEL * R2) return;
    const int d = i / R2, c = i % R2;
    O[i] = (c < RANK) ? A[d * RANK + c] : B[d * RANK + (c - RANK)];
}

// O[r, d] = r<R ? A[d, r] : B[d, r-R]     (shape [R2, D] — transposed concat)
__global__ void concat2T(const float* __restrict__ A, const float* __restrict__ B,
                         float* __restrict__ O)
{
    const int i = blockIdx.x * blockDim.x + threadIdx.x;
    if (i >= R2 * D_MODEL) return;
    const int r = i / D_MODEL, d = i % D_MODEL;
    O[i] = (r < RANK) ? A[(long)d * RANK + r] : B[(long)d * RANK + (r - RANK)];
}

// O[r, d] = A[d, r]                        (shape [R, D])
__global__ void transpK(const float* __restrict__ A, float* __restrict__ O)
{
    const int i = blockIdx.x * blockDim.x + threadIdx.x;
    if (i >= RANK * D_MODEL) return;
    const int r = i / D_MODEL, d = i % D_MODEL;
    O[i] = A[(long)d * RANK + r];
}

__global__ void biasvec_k(const float* __restrict__ bb, const float* __restrict__ bt,
                          const float* __restrict__ alpha, float* __restrict__ bv)
{
    const int i = blockIdx.x * blockDim.x + threadIdx.x;
    if (i < D_MODEL) bv[i] = bb[i] + alpha[0] * bt[i];
}

// ---------------- launch ------------------------------------------------------
extern "C" void kernel_launch(void* const* d_in, const int* in_sizes, int n_in,
                              void* d_out, int out_size)
{
    const float* x      = (const float*)d_in[0];
    const float* Wq     = (const float*)d_in[1];
    const float* Wk     = (const float*)d_in[2];
    const float* Wo     = (const float*)d_in[3];
    const float* U_b    = (const float*)d_in[4];
    const float* V_b    = (const float*)d_in[5];
    const float* W_b    = (const float*)d_in[6];
    const float* bias_b = (const float*)d_in[7];
    const float* U_t    = (const float*)d_in[8];
    const float* V_t    = (const float*)d_in[9];
    const float* W_t    = (const float*)d_in[10];
    const float* X_t    = (const float*)d_in[11];
    const float* bias_t = (const float*)d_in[12];
    const float* alpha  = (const float*)d_in[13];
    float* out = (float*)d_out;

    float *Q, *Km, *Z, *P, *A2, *C2, *G, *zt, *VcT, *WcT, *XtT, *Uc, *bv, *cs;
    cudaGetSymbolAddress((void**)&Q,   g_Q);
    cudaGetSymbolAddress((void**)&Km,  g_Km);
    cudaGetSymbolAddress((void**)&Z,   g_Z);
    cudaGetSymbolAddress((void**)&P,   g_P);
    cudaGetSymbolAddress((void**)&A2,  g_A2);
    cudaGetSymbolAddress((void**)&C2,  g_C2);
    cudaGetSymbolAddress((void**)&G,   g_G);
    cudaGetSymbolAddress((void**)&zt,  g_zt);
    cudaGetSymbolAddress((void**)&VcT, g_VcT);
    cudaGetSymbolAddress((void**)&WcT, g_WcT);
    cudaGetSymbolAddress((void**)&XtT, g_XtT);
    cudaGetSymbolAddress((void**)&Uc,  g_Uc);
    cudaGetSymbolAddress((void**)&bv,  g_bv);
    cudaGetSymbolAddress((void**)&cs,  g_cs);

    cudaFuncSetAttribute(gemm_bf3<false>, cudaFuncAttributeMaxDynamicSharedMemorySize, GEMM_SMEM);
    cudaFuncSetAttribute(gemm_bf3<true>,  cudaFuncAttributeMaxDynamicSharedMemorySize, GEMM_SMEM);

    // weight prep
    const int nc = (D_MODEL * R2 + 255) / 256;
    concat2T<<<nc, 256>>>(V_b, V_t, VcT);
    concat2T<<<nc, 256>>>(W_b, W_t, WcT);
    concat2 <<<nc, 256>>>(U_b, U_t, Uc);
    transpK <<<(RANK * D_MODEL + 255) / 256, 256>>>(X_t, XtT);
    biasvec_k<<<4, 256>>>(bias_b, bias_t, alpha, bv);

    // Q = x @ Wq.T ; K = x @ Wk.T
    dim3 gDD(D_MODEL / 128, MTOT / 128);
    gemm_bf3<false><<<gDD, 256, GEMM_SMEM>>>(x, Wq, Q,  D_MODEL, D_MODEL, nullptr);
    gemm_bf3<false><<<gDD, 256, GEMM_SMEM>>>(x, Wk, Km, D_MODEL, D_MODEL, nullptr);

    // Z = cumsum(x, axis=T) / counts
    dim3 gsx(D_MODEL / 128, NCH, BATCH);
    scan_partial<<<gsx, 128>>>(x, Z, cs, D_MODEL);
    scan_offsets<<<(BATCH * D_MODEL + 255) / 256, 256>>>(cs, D_MODEL);
    scan_apply<true><<<4096, 256>>>(Z, cs, D_MODEL);

    // A2 = Q @ VcT.T ; C2 = K @ WcT.T ; zt = Z @ XtT.T
    dim3 gR2(R2 / 128, MTOT / 128);
    gemm_bf3<false><<<gR2, 256, GEMM_SMEM>>>(Q,  VcT, A2, R2,   D_MODEL, nullptr);
    gemm_bf3<false><<<gR2, 256, GEMM_SMEM>>>(Km, WcT, C2, R2,   D_MODEL, nullptr);
    dim3 gR1(RANK / 128, MTOT / 128);
    gemm_bf3<false><<<gR1, 256, GEMM_SMEM>>>(Z,  XtT, zt, RANK, D_MODEL, nullptr);

    // causal cumsum over C2 (both halves), in place
    dim3 gsc(R2 / 128, NCH, BATCH);
    scan_partial<<<gsc, 128>>>(C2, C2, cs, R2);
    scan_offsets<<<(BATCH * R2 + 255) / 256, 256>>>(cs, R2);
    scan_apply<false><<<2048, 256>>>(C2, cs, R2);

    // G = [a_b*c_b/cnt | alpha*a_t*z_t*c_t/cnt]
    build_g<<<(MTOT * RANK + 255) / 256, 256>>>(A2, C2, zt, alpha, G);

    // P = G @ Uc.T + (bias_b + alpha*bias_t) ; out = P @ Wo.T
    gemm_bf3<true ><<<gDD, 256, GEMM_SMEM>>>(G, Uc, P,   D_MODEL, R2,      bv);
    gemm_bf3<false><<<gDD, 256, GEMM_SMEM>>>(P, Wo, out, D_MODEL, D_MODEL, nullptr);
}

// round 4
// speedup vs baseline: 3.5006x; 1.7761x over previous
#include <cuda_runtime.h>
#include <cuda_bf16.h>
#include <cstdint>

// Problem constants (fixed shapes)
#define D_MODEL 1024
#define RANK    256
#define R2      (2*RANK)     // 512
#define NPROJ   (R2 + R2 + RANK)  // 1280 = [A2(512) | C2(512) | zt(256)]
#define BATCH   4
#define SEQ     2048
#define MTOT    (BATCH*SEQ)  // 8192
#define TCH     128
#define NCH     (SEQ/TCH)    // 16

// ---------------- scratch (device globals; no cudaMalloc allowed) ------------
__device__ float g_H  [MTOT*NPROJ];        // fused projection output
__device__ float g_G  [MTOT*R2];
__device__ float g_WqT[D_MODEL*D_MODEL];
__device__ float g_WkT[D_MODEL*D_MODEL];
__device__ float g_VcT[R2*D_MODEL];
__device__ float g_WcT[R2*D_MODEL];
__device__ float g_UcT[R2*D_MODEL];
__device__ float g_Bp [NPROJ*D_MODEL];     // [WqvT(512) | WkwT(512) | XtT(256)] x D
__device__ float g_UWo[D_MODEL*R2];
__device__ float g_bv [D_MODEL];
__device__ float g_bo [D_MODEL];
__device__ float g_cs [BATCH*NCH*R2];

// ====================== mma.sync helpers =====================================
#define LDSM_X4(R, A) \
    asm volatile("ldmatrix.sync.aligned.m8n8.x4.shared.b16 {%0,%1,%2,%3}, [%4];" \
        : "=r"((R)[0]), "=r"((R)[1]), "=r"((R)[2]), "=r"((R)[3]) : "r"(A))
#define LDSM_X2(R, A) \
    asm volatile("ldmatrix.sync.aligned.m8n8.x2.shared.b16 {%0,%1}, [%2];" \
        : "=r"((R)[0]), "=r"((R)[1]) : "r"(A))
#define MMA_BF16(D, Ar, Br) \
    asm volatile("mma.sync.aligned.m16n8k16.row.col.f32.bf16.bf16.f32 " \
        "{%0,%1,%2,%3}, {%4,%5,%6,%7}, {%8,%9}, {%0,%1,%2,%3};" \
        : "+f"((D)[0]), "+f"((D)[1]), "+f"((D)[2]), "+f"((D)[3]) \
        : "r"((Ar)[0]), "r"((Ar)[1]), "r"((Ar)[2]), "r"((Ar)[3]), \
          "r"((Br)[0]), "r"((Br)[1]))

__device__ __forceinline__ uint32_t smem_u32(const void* p) {
    uint32_t a;
    asm("{ .reg .u64 t; cvta.to.shared.u64 t, %1; cvt.u32.u64 %0, t; }" : "=r"(a) : "l"(p));
    return a;
}

// paired-row swizzled byte offset for element chunk (m in [0,128), c in [0,4))
__device__ __forceinline__ uint32_t swoff(int m, int c) {
    const int p  = m >> 1;
    const int cc = (((m & 1) << 2) | c) ^ (p & 7);
    return (uint32_t)(p * 128 + cc * 16);
}

__device__ __forceinline__ uint32_t pack2(__nv_bfloat16 x, __nv_bfloat16 y) {
    return (uint32_t)__bfloat16_as_ushort(x) | ((uint32_t)__bfloat16_as_ushort(y) << 16);
}

__device__ __forceinline__ void split_sts(float4 v0, float4 v1, char* hp, char* lp) {
    float s[8] = {v0.x, v0.y, v0.z, v0.w, v1.x, v1.y, v1.z, v1.w};
    __nv_bfloat16 h[8], l[8];
#pragma unroll
    for (int q = 0; q < 8; q++) {
        h[q] = __float2bfloat16(s[q]);
        l[q] = __float2bfloat16(s[q] - __bfloat162float(h[q]));
    }
    uint4 H, L;
    H.x = pack2(h[0], h[1]); H.y = pack2(h[2], h[3]);
    H.z = pack2(h[4], h[5]); H.w = pack2(h[6], h[7]);
    L.x = pack2(l[0], l[1]); L.y = pack2(l[2], l[3]);
    L.z = pack2(l[4], l[5]); L.w = pack2(l[6], l[7]);
    *(uint4*)hp = H;
    *(uint4*)lp = L;
}

// ====================== 3xBF16-split tensor GEMM =============================
// C[M,N] = A[M,K] @ B[N,K]^T  (both row-major K-major). 128x128 CTA, BK=32.
#define TILE_B   8192
#define BUF_B    32768
#define GEMM_SMEM 65536

template<bool BIAS>
__global__ __launch_bounds__(256, 1)
void gemm_bf3(const float* __restrict__ A, const float* __restrict__ B,
              float* __restrict__ C, int N, int K, const float* __restrict__ bias)
{
    extern __shared__ __align__(128) char sm[];
    const uint32_t sb = smem_u32(sm);
    const int tid  = threadIdx.x;
    const int wid  = tid >> 5, lane = tid & 31;
    const int warpM = wid & 1, warpN = wid >> 1;
    const long bm = (long)blockIdx.y * 128, bn = (long)blockIdx.x * 128;

    uint32_t offA[4][2], offB[4][2];
#pragma unroll
    for (int i = 0; i < 4; i++) {
        const int m = warpM * 64 + i * 16 + (lane & 15);
#pragma unroll
        for (int kg = 0; kg < 2; kg++)
            offA[i][kg] = swoff(m, 2 * kg + (lane >> 4));
    }
#pragma unroll
    for (int j = 0; j < 4; j++) {
        const int n = warpN * 32 + j * 8 + (lane & 7);
#pragma unroll
        for (int kg = 0; kg < 2; kg++)
            offB[j][kg] = swoff(n, 2 * kg + ((lane >> 3) & 1));
    }

    const int r0 = tid >> 2, c0 = tid & 3;
    const uint32_t so0 = swoff(r0, c0), so1 = swoff(r0 + 64, c0);
    const float* Ag0 = A + (bm + r0) * K + c0 * 8;
    const float* Ag1 = Ag0 + 64L * K;
    const float* Bg0 = B + (bn + r0) * K + c0 * 8;
    const float* Bg1 = Bg0 + 64L * K;

    float4 pa0, pa1, pa2, pa3, pb0, pb1, pb2, pb3;
    auto ldg = [&](int kt) {
        const long o = (long)kt * 32;
        pa0 = *(const float4*)(Ag0 + o); pa1 = *(const float4*)(Ag0 + o + 4);
        pa2 = *(const float4*)(Ag1 + o); pa3 = *(const float4*)(Ag1 + o + 4);
        pb0 = *(const float4*)(Bg0 + o); pb1 = *(const float4*)(Bg0 + o + 4);
        pb2 = *(const float4*)(Bg1 + o); pb3 = *(const float4*)(Bg1 + o + 4);
    };
    auto sts = [&](int buf) {
        char* base = sm + buf * BUF_B;
        split_sts(pa0, pa1, base + so0,              base + TILE_B + so0);
        split_sts(pa2, pa3, base + so1,              base + TILE_B + so1);
        split_sts(pb0, pb1, base + 2*TILE_B + so0,   base + 3*TILE_B + so0);
        split_sts(pb2, pb3, base + 2*TILE_B + so1,   base + 3*TILE_B + so1);
    };

    float acc[4][4][4];
#pragma unroll
    for (int i = 0; i < 4; i++)
#pragma unroll
        for (int j = 0; j < 4; j++)
#pragma unroll
            for (int q = 0; q < 4; q++) acc[i][j][q] = 0.f;

    const int nk = K / 32;
    ldg(0);
    sts(0);
    __syncthreads();

#pragma unroll 1
    for (int kt = 0; kt < nk; kt++) {
        const bool pref = (kt + 1 < nk);
        if (pref) ldg(kt + 1);

        const uint32_t bb = sb + (kt & 1) * BUF_B;
#pragma unroll
        for (int kg = 0; kg < 2; kg++) {
            uint32_t ah[4][4], al[4][4], bh[4][2], bl[4][2];
#pragma unroll
            for (int i = 0; i < 4; i++) {
                LDSM_X4(ah[i], bb + offA[i][kg]);
                LDSM_X4(al[i], bb + TILE_B + offA[i][kg]);
            }
#pragma unroll
            for (int j = 0; j < 4; j++) {
                LDSM_X2(bh[j], bb + 2*TILE_B + offB[j][kg]);
                LDSM_X2(bl[j], bb + 3*TILE_B + offB[j][kg]);
            }
#pragma unroll
            for (int i = 0; i < 4; i++)
#pragma unroll
                for (int j = 0; j < 4; j++) {
                    MMA_BF16(acc[i][j], ah[i], bh[j]);
                    MMA_BF16(acc[i][j], ah[i], bl[j]);
                    MMA_BF16(acc[i][j], al[i], bh[j]);
                }
        }
        if (pref) sts((kt + 1) & 1);
        __syncthreads();
    }

    const int g = lane >> 2, tg = lane & 3;
#pragma unroll
    for (int i = 0; i < 4; i++) {
        const long row = bm + warpM * 64 + i * 16 + g;
#pragma unroll
        for (int j = 0; j < 4; j++) {
            const int col = (int)bn + warpN * 32 + j * 8 + 2 * tg;
            float b0 = 0.f, b1 = 0.f;
            if (BIAS) { b0 = bias[col]; b1 = bias[col + 1]; }
            float2 v0 = make_float2(acc[i][j][0] + b0, acc[i][j][1] + b1);
            float2 v1 = make_float2(acc[i][j][2] + b0, acc[i][j][3] + b1);
            *(float2*)(C + row * N + col)       = v0;
            *(float2*)(C + (row + 8) * N + col) = v1;
        }
    }
}

// ---------------- causal cumulative sum (3-pass, strided columns) -----------
__global__ void scan_partial(const float* __restrict__ Y, float* __restrict__ O,
                             float* __restrict__ cs, int S, int C)
{
    const int col = blockIdx.x * 128 + threadIdx.x;
    const int ch  = blockIdx.y;
    const int b   = blockIdx.z;
    const long base = ((long)b * SEQ + (long)ch * TCH) * S + col;
    float run = 0.f;
    for (int t = 0; t < TCH; t++) {
        run += Y[base + (long)t * S];
        O[base + (long)t * S] = run;
    }
    cs[((long)b * NCH + ch) * C + col] = run;
}

__global__ void scan_offsets(float* __restrict__ cs, int C)
{
    const int i = blockIdx.x * blockDim.x + threadIdx.x;
    if (i >= BATCH * C) return;
    const int b = i / C, col = i % C;
    float off = 0.f;
    for (int ch = 0; ch < NCH; ch++) {
        const long idx = ((long)b * NCH + ch) * C + col;
        const float v = cs[idx];
        cs[idx] = off;
        off += v;
    }
}

template<bool DIVIDE>
__global__ void scan_apply(float* __restrict__ O, const float* __restrict__ cs,
                           int S, int C)
{
    const long total = (long)MTOT * C;
    for (long i = (long)blockIdx.x * blockDim.x + threadIdx.x; i < total;
         i += (long)gridDim.x * blockDim.x) {
        const int  c  = (int)(i % C);
        const long mt = i / C;
        const int  t  = (int)(mt % SEQ);
        const int  b  = (int)(mt / SEQ);
        const int  ch = t / TCH;
        float v = O[mt * S + c] + cs[((long)b * NCH + ch) * C + c];
        if (DIVIDE) v *= 1.0f / (float)(t + 1);
        O[mt * S + c] = v;
    }
}

// ---------------- elementwise glue ------------------------------------------
// H row layout: [a_b(0..256) | a_t(256..512) | c_b(512..768) | c_t(768..1024) | z(1024..1280)]
__global__ void build_g(const float* __restrict__ H, const float* __restrict__ alpha,
                        float* __restrict__ G)
{
    const int i = blockIdx.x * blockDim.x + threadIdx.x;
    if (i >= MTOT * RANK) return;
    const int m = i / RANK, r = i % RANK;
    const float inv = 1.0f / (float)((m % SEQ) + 1);
    const float* h = H + (long)m * NPROJ;
    const float gb = h[r] * h[512 + r] * inv;
    const float gt = alpha[0] * h[256 + r] * h[1024 + r] * h[768 + r] * inv;
    float* g = G + (long)m * R2;
    g[r]        = gb;
    g[RANK + r] = gt;
}

// O[r, d] = r<R ? A[d, r] : B[d, r-R]     (shape [R2, D] — transposed concat)
__global__ void concat2T(const float* __restrict__ A, const float* __restrict__ B,
                         float* __restrict__ O)
{
    const int i = blockIdx.x * blockDim.x + threadIdx.x;
    if (i >= R2 * D_MODEL) return;
    const int r = i / D_MODEL, d = i % D_MODEL;
    O[i] = (r < RANK) ? A[(long)d * RANK + r] : B[(long)d * RANK + (r - RANK)];
}

// O[r, d] = A[d, r]                        (shape [R, D])
__global__ void transpK(const float* __restrict__ A, float* __restrict__ O)
{
    const int i = blockIdx.x * blockDim.x + threadIdx.x;
    if (i >= RANK * D_MODEL) return;
    const int r = i / D_MODEL, d = i % D_MODEL;
    O[i] = A[(long)d * RANK + r];
}

// 1024x1024 tiled transpose
__global__ void transpose1024(const float* __restrict__ A, float* __restrict__ O)
{
    __shared__ float t[32][33];
    const int bx = blockIdx.x * 32, by = blockIdx.y * 32;
    const int tx = threadIdx.x, ty = threadIdx.y;
#pragma unroll
    for (int j = 0; j < 32; j += 8)
        t[ty + j][tx] = A[(long)(by + ty + j) * D_MODEL + bx + tx];
    __syncthreads();
#pragma unroll
    for (int j = 0; j < 32; j += 8)
        O[(long)(bx + ty + j) * D_MODEL + by + tx] = t[tx][ty + j];
}

__global__ void biasvec_k(const float* __restrict__ bb, const float* __restrict__ bt,
                          const float* __restrict__ alpha, float* __restrict__ bv)
{
    const int i = blockIdx.x * blockDim.x + threadIdx.x;
    if (i < D_MODEL) bv[i] = bb[i] + alpha[0] * bt[i];
}

// bo[d] = sum_e Wo[d,e] * bv[e]   (warp per row)
__global__ void bo_kernel(const float* __restrict__ Wo, const float* __restrict__ bv,
                          float* __restrict__ bo)
{
    const int w = (blockIdx.x * blockDim.x + threadIdx.x) >> 5;
    const int lane = threadIdx.x & 31;
    if (w >= D_MODEL) return;
    float s = 0.f;
    for (int e = lane; e < D_MODEL; e += 32)
        s += Wo[(long)w * D_MODEL + e] * bv[e];
#pragma unroll
    for (int o = 16; o; o >>= 1) s += __shfl_xor_sync(0xFFFFFFFFu, s, o);
    if (lane == 0) bo[w] = s;
}

// ---------------- launch ------------------------------------------------------
extern "C" void kernel_launch(void* const* d_in, const int* in_sizes, int n_in,
                              void* d_out, int out_size)
{
    const float* x      = (const float*)d_in[0];
    const float* Wq     = (const float*)d_in[1];
    const float* Wk     = (const float*)d_in[2];
    const float* Wo     = (const float*)d_in[3];
    const float* U_b    = (const float*)d_in[4];
    const float* V_b    = (const float*)d_in[5];
    const float* W_b    = (const float*)d_in[6];
    const float* bias_b = (const float*)d_in[7];
    const float* U_t    = (const float*)d_in[8];
    const float* V_t    = (const float*)d_in[9];
    const float* W_t    = (const float*)d_in[10];
    const float* X_t    = (const float*)d_in[11];
    const float* bias_t = (const float*)d_in[12];
    const float* alpha  = (const float*)d_in[13];
    float* out = (float*)d_out;

    float *H, *G, *WqT, *WkT, *VcT, *WcT, *UcT, *Bp, *UWo, *bv, *bo, *cs;
    cudaGetSymbolAddress((void**)&H,   g_H);
    cudaGetSymbolAddress((void**)&G,   g_G);
    cudaGetSymbolAddress((void**)&WqT, g_WqT);
    cudaGetSymbolAddress((void**)&WkT, g_WkT);
    cudaGetSymbolAddress((void**)&VcT, g_VcT);
    cudaGetSymbolAddress((void**)&WcT, g_WcT);
    cudaGetSymbolAddress((void**)&UcT, g_UcT);
    cudaGetSymbolAddress((void**)&Bp,  g_Bp);
    cudaGetSymbolAddress((void**)&UWo, g_UWo);
    cudaGetSymbolAddress((void**)&bv,  g_bv);
    cudaGetSymbolAddress((void**)&bo,  g_bo);
    cudaGetSymbolAddress((void**)&cs,  g_cs);

    cudaFuncSetAttribute(gemm_bf3<false>, cudaFuncAttributeMaxDynamicSharedMemorySize, GEMM_SMEM);
    cudaFuncSetAttribute(gemm_bf3<true>,  cudaFuncAttributeMaxDynamicSharedMemorySize, GEMM_SMEM);

    // ---- weight prep ----
    dim3 tgrid(32, 32), tblk(32, 8);
    transpose1024<<<tgrid, tblk>>>(Wq, WqT);
    transpose1024<<<tgrid, tblk>>>(Wk, WkT);

    const int nc = (R2 * D_MODEL + 255) / 256;
    concat2T<<<nc, 256>>>(V_b, V_t, VcT);
    concat2T<<<nc, 256>>>(W_b, W_t, WcT);
    concat2T<<<nc, 256>>>(U_b, U_t, UcT);
    transpK <<<(RANK * D_MODEL + 255) / 256, 256>>>(X_t, Bp + (long)2 * R2 * D_MODEL);

    biasvec_k<<<4, 256>>>(bias_b, bias_t, alpha, bv);
    bo_kernel<<<128, 256>>>(Wo, bv, bo);

    // WqvT = VcT @ WqT^T   [512,1024] rows 0..512 of Bp
    dim3 gW(D_MODEL / 128, R2 / 128);
    gemm_bf3<false><<<gW, 256, GEMM_SMEM>>>(VcT, WqT, Bp, D_MODEL, D_MODEL, nullptr);
    // WkwT = WcT @ WkT^T   rows 512..1024 of Bp
    gemm_bf3<false><<<gW, 256, GEMM_SMEM>>>(WcT, WkT, Bp + (long)R2 * D_MODEL, D_MODEL, D_MODEL, nullptr);
    // UWo = Wo @ UcT^T     [1024, 512]
    dim3 gU(R2 / 128, D_MODEL / 128);
    gemm_bf3<false><<<gU, 256, GEMM_SMEM>>>(Wo, UcT, UWo, R2, D_MODEL, nullptr);

    // ---- main path ----
    // H = x @ Bp^T   [8192, 1280]
    dim3 gH(NPROJ / 128, MTOT / 128);
    gemm_bf3<false><<<gH, 256, GEMM_SMEM>>>(x, Bp, H, NPROJ, D_MODEL, nullptr);

    // causal cumsum over C2 columns [512..1024)
    dim3 gs1(R2 / 128, NCH, BATCH);
    scan_partial<<<gs1, 128>>>(H + 512, H + 512, cs, NPROJ, R2);
    scan_offsets<<<(BATCH * R2 + 255) / 256, 256>>>(cs, R2);
    scan_apply<false><<<2048, 256>>>(H + 512, cs, NPROJ, R2);

    // causal cumsum+divide over zt columns [1024..1280)
    dim3 gs2(RANK / 128, NCH, BATCH);
    scan_partial<<<gs2, 128>>>(H + 1024, H + 1024, cs, NPROJ, RANK);
    scan_offsets<<<(BATCH * RANK + 255) / 256, 256>>>(cs, RANK);
    scan_apply<true><<<1024, 256>>>(H + 1024, cs, NPROJ, RANK);

    // G = [a_b*c_b/cnt | alpha*a_t*z*c_t/cnt]
    build_g<<<(MTOT * RANK + 255) / 256, 256>>>(H, alpha, G);

    // out = G @ UWo^T + bo   [8192, 1024]
    dim3 gO(D_MODEL / 128, MTOT / 128);
    gemm_bf3<true><<<gO, 256, GEMM_SMEM>>>(G, UWo, out, D_MODEL, R2, bo);
}

// round 5
// speedup vs baseline: 5.5867x; 1.5960x over previous
#include <cuda_runtime.h>
#include <cuda_bf16.h>
#include <cstdint>

// Problem constants (fixed shapes)
#define D_MODEL 1024
#define RANK    256
#define R2      (2*RANK)          // 512
#define NPROJ   (R2 + R2 + RANK)  // 1280 = [a_b|a_t | c_b|c_t | z]
#define BATCH   4
#define SEQ     2048
#define MTOT    (BATCH*SEQ)       // 8192
#define TCH     128
#define NCH     (SEQ/TCH)         // 16
#define SCANC   (R2 + RANK)       // 768 scanned columns

// ---------------- scratch (device globals; no cudaMalloc allowed) ------------
__device__ float         g_H   [MTOT*NPROJ];
__device__ __nv_bfloat16 g_xh  [MTOT*D_MODEL];
__device__ __nv_bfloat16 g_xl  [MTOT*D_MODEL];
__device__ __nv_bfloat16 g_Gh  [MTOT*R2];
__device__ __nv_bfloat16 g_Gl  [MTOT*R2];
__device__ __nv_bfloat16 g_Bph [NPROJ*D_MODEL];
__device__ __nv_bfloat16 g_Bpl [NPROJ*D_MODEL];
__device__ __nv_bfloat16 g_UWoh[D_MODEL*R2];
__device__ __nv_bfloat16 g_UWol[D_MODEL*R2];
__device__ float g_WqT[D_MODEL*D_MODEL];
__device__ float g_WkT[D_MODEL*D_MODEL];
__device__ float g_VcT[R2*D_MODEL];
__device__ float g_WcT[R2*D_MODEL];
__device__ float g_UcT[R2*D_MODEL];
__device__ float g_bo [D_MODEL];
__device__ float g_cs [BATCH*NCH*SCANC];

// ====================== helpers ==============================================
#define LDSM_X4(R, A) \
    asm volatile("ldmatrix.sync.aligned.m8n8.x4.shared.b16 {%0,%1,%2,%3}, [%4];" \
        : "=r"((R)[0]), "=r"((R)[1]), "=r"((R)[2]), "=r"((R)[3]) : "r"(A))
#define LDSM_X2(R, A) \
    asm volatile("ldmatrix.sync.aligned.m8n8.x2.shared.b16 {%0,%1}, [%2];" \
        : "=r"((R)[0]), "=r"((R)[1]) : "r"(A))
#define MMA_BF16(D, Ar, Br) \
    asm volatile("mma.sync.aligned.m16n8k16.row.col.f32.bf16.bf16.f32 " \
        "{%0,%1,%2,%3}, {%4,%5,%6,%7}, {%8,%9}, {%0,%1,%2,%3};" \
        : "+f"((D)[0]), "+f"((D)[1]), "+f"((D)[2]), "+f"((D)[3]) \
        : "r"((Ar)[0]), "r"((Ar)[1]), "r"((Ar)[2]), "r"((Ar)[3]), \
          "r"((Br)[0]), "r"((Br)[1]))

__device__ __forceinline__ uint32_t smem_u32(const void* p) {
    uint32_t a;
    asm("{ .reg .u64 t; cvta.to.shared.u64 t, %1; cvt.u32.u64 %0, t; }" : "=r"(a) : "l"(p));
    return a;
}

// paired-row swizzled byte offset for element chunk (m in [0,128), c in [0,4))
__device__ __forceinline__ uint32_t swoff(int m, int c) {
    const int p  = m >> 1;
    const int cc = (((m & 1) << 2) | c) ^ (p & 7);
    return (uint32_t)(p * 128 + cc * 16);
}

__device__ __forceinline__ uint32_t pack2(__nv_bfloat16 x, __nv_bfloat16 y) {
    return (uint32_t)__bfloat16_as_ushort(x) | ((uint32_t)__bfloat16_as_ushort(y) << 16);
}

__device__ __forceinline__ void bf_split(float v, __nv_bfloat16& h, __nv_bfloat16& l) {
    h = __float2bfloat16(v);
    l = __float2bfloat16(v - __bfloat162float(h));
}

__device__ __forceinline__ void cpasync16(uint32_t dst, const void* src) {
    asm volatile("cp.async.cg.shared.global [%0], [%1], 16;" :: "r"(dst), "l"(src));
}
#define CP_COMMIT() asm volatile("cp.async.commit_group;" ::: "memory")
#define CP_WAIT2()  asm volatile("cp.async.wait_group 2;"  ::: "memory")

__device__ __forceinline__ void split_sts(float4 v0, float4 v1, char* hp, char* lp) {
    float s[8] = {v0.x, v0.y, v0.z, v0.w, v1.x, v1.y, v1.z, v1.w};
    __nv_bfloat16 h[8], l[8];
#pragma unroll
    for (int q = 0; q < 8; q++) bf_split(s[q], h[q], l[q]);
    uint4 H, L;
    H.x = pack2(h[0], h[1]); H.y = pack2(h[2], h[3]);
    H.z = pack2(h[4], h[5]); H.w = pack2(h[6], h[7]);
    L.x = pack2(l[0], l[1]); L.y = pack2(l[2], l[3]);
    L.z = pack2(l[4], l[5]); L.w = pack2(l[6], l[7]);
    *(uint4*)hp = H;
    *(uint4*)lp = L;
}

// ====================== pre-split bf16 tensor GEMM (main path) ===============
// C[M,N] = (Ah+Al)[M,K] @ (Bh+Bl)[N,K]^T with 3-term product; cp.async 4-stage.
#define TILE_B     8192
#define STAGE_B    32768
#define PRE_SMEM   (4*STAGE_B)   // 128 KB

template<bool BIAS>
__global__ __launch_bounds__(256, 1)
void gemm_pre(const __nv_bfloat16* __restrict__ Ah_g, const __nv_bfloat16* __restrict__ Al_g,
              const __nv_bfloat16* __restrict__ Bh_g, const __nv_bfloat16* __restrict__ Bl_g,
              float* __restrict__ C, int N, int K, const float* __restrict__ bias)
{
    extern __shared__ __align__(128) char sm[];
    const uint32_t sb = smem_u32(sm);
    const int tid  = threadIdx.x;
    const int wid  = tid >> 5, lane = tid & 31;
    const int warpM = wid & 1, warpN = wid >> 1;
    const long bm = (long)blockIdx.y * 128, bn = (long)blockIdx.x * 128;

    uint32_t offA[4][2], offB[4][2];
#pragma unroll
    for (int i = 0; i < 4; i++) {
        const int m = warpM * 64 + i * 16 + (lane & 15);
#pragma unroll
        for (int kg = 0; kg < 2; kg++)
            offA[i][kg] = swoff(m, 2 * kg + (lane >> 4));
    }
#pragma unroll
    for (int j = 0; j < 4; j++) {
        const int n = warpN * 32 + j * 8 + (lane & 7);
#pragma unroll
        for (int kg = 0; kg < 2; kg++)
            offB[j][kg] = swoff(n, 2 * kg + ((lane >> 3) & 1));
    }

    auto issue = [&](int kt) {
        const uint32_t base = sb + (uint32_t)(kt & 3) * STAGE_B;
#pragma unroll
        for (int q = 0; q < 2; q++) {
            const int ci = tid + 256 * q;
            const int m = ci >> 2, c = ci & 3;
            const uint32_t so = swoff(m, c);
            const long goA = (bm + m) * (long)K + (long)kt * 32 + c * 8;
            const long goB = (bn + m) * (long)K + (long)kt * 32 + c * 8;
            cpasync16(base + so,             Ah_g + goA);
            cpasync16(base + TILE_B + so,    Al_g + goA);
            cpasync16(base + 2*TILE_B + so,  Bh_g + goB);
            cpasync16(base + 3*TILE_B + so,  Bl_g + goB);
        }
    };

    float acc[4][4][4];
#pragma unroll
    for (int i = 0; i < 4; i++)
#pragma unroll
        for (int j = 0; j < 4; j++)
#pragma unroll
            for (int q = 0; q < 4; q++) acc[i][j][q] = 0.f;

    const int nk = K / 32;   // >= 16 always
    issue(0); CP_COMMIT();
    issue(1); CP_COMMIT();
    issue(2); CP_COMMIT();

#pragma unroll 1
    for (int kt = 0; kt < nk; kt++) {
        CP_WAIT2();
        __syncthreads();
        if (kt + 3 < nk) issue(kt + 3);
        CP_COMMIT();

        const uint32_t bb = sb + (uint32_t)(kt & 3) * STAGE_B;
#pragma unroll
        for (int kg = 0; kg < 2; kg++) {
            uint32_t ah[4][4], al[4][4], bh[4][2], bl[4][2];
#pragma unroll
            for (int i = 0; i < 4; i++) {
                LDSM_X4(ah[i], bb + offA[i][kg]);
                LDSM_X4(al[i], bb + TILE_B + offA[i][kg]);
            }
#pragma unroll
            for (int j = 0; j < 4; j++) {
                LDSM_X2(bh[j], bb + 2*TILE_B + offB[j][kg]);
                LDSM_X2(bl[j], bb + 3*TILE_B + offB[j][kg]);
            }
#pragma unroll
            for (int i = 0; i < 4; i++)
#pragma unroll
                for (int j = 0; j < 4; j++) {
                    MMA_BF16(acc[i][j], ah[i], bh[j]);
                    MMA_BF16(acc[i][j], ah[i], bl[j]);
                    MMA_BF16(acc[i][j], al[i], bh[j]);
                }
        }
    }

    const int g = lane >> 2, tg = lane & 3;
#pragma unroll
    for (int i = 0; i < 4; i++) {
        const long row = bm + warpM * 64 + i * 16 + g;
#pragma unroll
        for (int j = 0; j < 4; j++) {
            const int col = (int)bn + warpN * 32 + j * 8 + 2 * tg;
            float b0 = 0.f, b1 = 0.f;
            if (BIAS) { b0 = bias[col]; b1 = bias[col + 1]; }
            float2 v0 = make_float2(acc[i][j][0] + b0, acc[i][j][1] + b1);
            float2 v1 = make_float2(acc[i][j][2] + b0, acc[i][j][3] + b1);
            *(float2*)(C + row * N + col)       = v0;
            *(float2*)(C + (row + 8) * N + col) = v1;
        }
    }
}

// ====================== fp32-input prep GEMM (batched, bf16-split output) ====
// z=0: Bp[0..512)   = VcT @ WqT^T ; z=1: Bp[512..1024) = WcT @ WkT^T
// z=2: UWo[1024,512] = Wo @ UcT^T
#define BUF_B    32768
#define PREP_SMEM 65536

__global__ __launch_bounds__(256, 1)
void gemm_prep(const float* __restrict__ VcT, const float* __restrict__ WqT,
               const float* __restrict__ WcT, const float* __restrict__ WkT,
               const float* __restrict__ Wo,  const float* __restrict__ UcT,
               __nv_bfloat16* __restrict__ Bph, __nv_bfloat16* __restrict__ Bpl,
               __nv_bfloat16* __restrict__ UWoh, __nv_bfloat16* __restrict__ UWol)
{
    const int z = blockIdx.z;
    const float *A, *B;
    __nv_bfloat16 *Ch, *Cl;
    int Mt, Nt, ldc, roff;
    if (z == 0)      { A = VcT; B = WqT; Ch = Bph;  Cl = Bpl;  Mt = 512;  Nt = 1024; ldc = 1024; roff = 0;   }
    else if (z == 1) { A = WcT; B = WkT; Ch = Bph;  Cl = Bpl;  Mt = 512;  Nt = 1024; ldc = 1024; roff = 512; }
    else             { A = Wo;  B = UcT; Ch = UWoh; Cl = UWol; Mt = 1024; Nt = 512;  ldc = 512;  roff = 0;   }
    if ((int)blockIdx.y * 128 >= Mt || (int)blockIdx.x * 128 >= Nt) return;
    const int K = 1024, N = Nt;

    extern __shared__ __align__(128) char sm[];
    const int tid  = threadIdx.x;
    const int wid  = tid >> 5, lane = tid & 31;
    const int warpM = wid & 1, warpN = wid >> 1;
    const long bm = (long)blockIdx.y * 128, bn = (long)blockIdx.x * 128;
    const uint32_t sb = smem_u32(sm);

    uint32_t offA[4][2], offB[4][2];
#pragma unroll
    for (int i = 0; i < 4; i++) {
        const int m = warpM * 64 + i * 16 + (lane & 15);
#pragma unroll
        for (int kg = 0; kg < 2; kg++)
            offA[i][kg] = swoff(m, 2 * kg + (lane >> 4));
    }
#pragma unroll
    for (int j = 0; j < 4; j++) {
        const int n = warpN * 32 + j * 8 + (lane & 7);
#pragma unroll
        for (int kg = 0; kg < 2; kg++)
            offB[j][kg] = swoff(n, 2 * kg + ((lane >> 3) & 1));
    }

    const int r0 = tid >> 2, c0 = tid & 3;
    const uint32_t so0 = swoff(r0, c0), so1 = swoff(r0 + 64, c0);
    const float* Ag0 = A + (bm + r0) * K + c0 * 8;
    const float* Ag1 = Ag0 + 64L * K;
    const float* Bg0 = B + (bn + r0) * K + c0 * 8;
    const float* Bg1 = Bg0 + 64L * K;

    float4 pa0, pa1, pa2, pa3, pb0, pb1, pb2, pb3;
    auto ldg = [&](int kt) {
        const long o = (long)kt * 32;
        pa0 = *(const float4*)(Ag0 + o); pa1 = *(const float4*)(Ag0 + o + 4);
        pa2 = *(const float4*)(Ag1 + o); pa3 = *(const float4*)(Ag1 + o + 4);
        pb0 = *(const float4*)(Bg0 + o); pb1 = *(const float4*)(Bg0 + o + 4);
        pb2 = *(const float4*)(Bg1 + o); pb3 = *(const float4*)(Bg1 + o + 4);
    };
    auto sts = [&](int buf) {
        char* base = sm + buf * BUF_B;
        split_sts(pa0, pa1, base + so0,            base + TILE_B + so0);
        split_sts(pa2, pa3, base + so1,            base + TILE_B + so1);
        split_sts(pb0, pb1, base + 2*TILE_B + so0, base + 3*TILE_B + so0);
        split_sts(pb2, pb3, base + 2*TILE_B + so1, base + 3*TILE_B + so1);
    };

    float acc[4][4][4];
#pragma unroll
    for (int i = 0; i < 4; i++)
#pragma unroll
        for (int j = 0; j < 4; j++)
#pragma unroll
            for (int q = 0; q < 4; q++) acc[i][j][q] = 0.f;

    const int nk = K / 32;
    ldg(0);
    sts(0);
    __syncthreads();

#pragma unroll 1
    for (int kt = 0; kt < nk; kt++) {
        const bool pref = (kt + 1 < nk);
        if (pref) ldg(kt + 1);
        const uint32_t bb = sb + (kt & 1) * BUF_B;
#pragma unroll
        for (int kg = 0; kg < 2; kg++) {
            uint32_t ah[4][4], al[4][4], bh[4][2], bl[4][2];
#pragma unroll
            for (int i = 0; i < 4; i++) {
                LDSM_X4(ah[i], bb + offA[i][kg]);
                LDSM_X4(al[i], bb + TILE_B + offA[i][kg]);
            }
#pragma unroll
            for (int j = 0; j < 4; j++) {
                LDSM_X2(bh[j], bb + 2*TILE_B + offB[j][kg]);
                LDSM_X2(bl[j], bb + 3*TILE_B + offB[j][kg]);
            }
#pragma unroll
            for (int i = 0; i < 4; i++)
#pragma unroll
                for (int j = 0; j < 4; j++) {
                    MMA_BF16(acc[i][j], ah[i], bh[j]);
                    MMA_BF16(acc[i][j], ah[i], bl[j]);
                    MMA_BF16(acc[i][j], al[i], bh[j]);
                }
        }
        if (pref) sts((kt + 1) & 1);
        __syncthreads();
    }

    // bf16 split epilogue
    const int g = lane >> 2, tg = lane & 3;
#pragma unroll
    for (int i = 0; i < 4; i++) {
        const long row = roff + bm + warpM * 64 + i * 16 + g;
#pragma unroll
        for (int j = 0; j < 4; j++) {
            const int col = (int)bn + warpN * 32 + j * 8 + 2 * tg;
            __nv_bfloat16 h0, l0, h1, l1;
#pragma unroll
            for (int half = 0; half < 2; half++) {
                const long r = row + half * 8;
                bf_split(acc[i][j][half*2 + 0], h0, l0);
                bf_split(acc[i][j][half*2 + 1], h1, l1);
                *(uint32_t*)(Ch + r * ldc + col) = pack2(h0, h1);
                *(uint32_t*)(Cl + r * ldc + col) = pack2(l0, l1);
            }
        }
    }
}

// ====================== batched tiled transpose / concat =====================
// z=0: Wq->WqT ; z=1: Wk->WkT ; z=2..7: {V_b,V_t,W_b,W_t,U_b,U_t} -> {VcT,WcT,UcT}
// z=8: X_t -> bf16-split rows [1024,1280) of Bph/Bpl
__global__ void trans_batched(const float* __restrict__ Wq, const float* __restrict__ Wk,
                              const float* __restrict__ V_b, const float* __restrict__ V_t,
                              const float* __restrict__ W_b, const float* __restrict__ W_t,
                              const float* __restrict__ U_b, const float* __restrict__ U_t,
                              const float* __restrict__ X_t,
                              float* __restrict__ WqT, float* __restrict__ WkT,
                              float* __restrict__ VcT, float* __restrict__ WcT,
                              float* __restrict__ UcT,
                              __nv_bfloat16* __restrict__ Bph, __nv_bfloat16* __restrict__ Bpl)
{
    __shared__ float t[32][33];
    const int z = blockIdx.z;
    const float* src; int Cin; float* dst = nullptr; int roff = 0; bool split = false;
    switch (z) {
        case 0: src = Wq;  Cin = 1024; dst = WqT; break;
        case 1: src = Wk;  Cin = 1024; dst = WkT; break;
        case 2: src = V_b; Cin = 256;  dst = VcT; roff = 0;    break;
        case 3: src = V_t; Cin = 256;  dst = VcT; roff = 256;  break;
        case 4: src = W_b; Cin = 256;  dst = WcT; roff = 0;    break;
        case 5: src = W_t; Cin = 256;  dst = WcT; roff = 256;  break;
        case 6: src = U_b; Cin = 256;  dst = UcT; roff = 0;    break;
        case 7: src = U_t; Cin = 256;  dst = UcT; roff = 256;  break;
        default: src = X_t; Cin = 256; split = true; roff = 1024; break;
    }
    const int bx = blockIdx.x, by = blockIdx.y;
    if (Cin == 256 && bx >= 8) return;
    const int tx = threadIdx.x, ty = threadIdx.y;
#pragma unroll
    for (int j = 0; j < 32; j += 8)
        t[ty + j][tx] = src[(long)(by * 32 + ty + j) * Cin + bx * 32 + tx];
    __syncthreads();
    if (!split) {
#pragma unroll
        for (int j = 0; j < 32; j += 8)
            dst[(long)(roff + bx * 32 + ty + j) * 1024 + by * 32 + tx] = t[tx][ty + j];
    } else {
#pragma unroll
        for (int j = 0; j < 32; j += 8) {
            __nv_bfloat16 h, l;
            bf_split(t[tx][ty + j], h, l);
            const long o = (long)(roff + bx * 32 + ty + j) * 1024 + by * 32 + tx;
            Bph[o] = h; Bpl[o] = l;
        }
    }
}

// ---------------- split x into bf16 hi/lo planes -----------------------------
__global__ void split_x(const float* __restrict__ x,
                        __nv_bfloat16* __restrict__ xh, __nv_bfloat16* __restrict__ xl)
{
    const long n4 = (long)MTOT * D_MODEL / 4;
    for (long i = (long)blockIdx.x * blockDim.x + threadIdx.x; i < n4;
         i += (long)gridDim.x * blockDim.x) {
        float4 v = ((const float4*)x)[i];
        __nv_bfloat16 h[4], l[4];
        bf_split(v.x, h[0], l[0]); bf_split(v.y, h[1], l[1]);
        bf_split(v.z, h[2], l[2]); bf_split(v.w, h[3], l[3]);
        uint2 H, L;
        H.x = pack2(h[0], h[1]); H.y = pack2(h[2], h[3]);
        L.x = pack2(l[0], l[1]); L.y = pack2(l[2], l[3]);
        ((uint2*)xh)[i] = H;
        ((uint2*)xl)[i] = L;
    }
}

// ---------------- causal cumulative scan (cols 512..1280 of H) --------------
__global__ void scan_partial(float* __restrict__ Hc, float* __restrict__ cs)
{
    const int col = blockIdx.x * 128 + threadIdx.x;   // 0..767
    const int ch  = blockIdx.y;
    const int b   = blockIdx.z;
    const long base = ((long)b * SEQ + (long)ch * TCH) * NPROJ + col;
    float run = 0.f;
    for (int t = 0; t < TCH; t++) {
        run += Hc[base + (long)t * NPROJ];
        Hc[base + (long)t * NPROJ] = run;
    }
    cs[((long)b * NCH + ch) * SCANC + col] = run;
}

__global__ void scan_offsets(float* __restrict__ cs)
{
    const int i = blockIdx.x * blockDim.x + threadIdx.x;
    if (i >= BATCH * SCANC) return;
    const int b = i / SCANC, col = i % SCANC;
    float off = 0.f;
    for (int ch = 0; ch < NCH; ch++) {
        const long idx = ((long)b * NCH + ch) * SCANC + col;
        const float v = cs[idx];
        cs[idx] = off;
        off += v;
    }
}

// ---------------- fused scan-apply + G build (bf16 split output) -------------
__global__ void apply_build(const float* __restrict__ H, const float* __restrict__ cs,
                            const float* __restrict__ alpha,
                            __nv_bfloat16* __restrict__ Gh, __nv_bfloat16* __restrict__ Gl)
{
    const int i = blockIdx.x * blockDim.x + threadIdx.x;
    if (i >= MTOT * RANK) return;
    const int m = i / RANK, r = i % RANK;
    const int t = m % SEQ, b = m / SEQ, ch = t / TCH;
    const float inv = 1.0f / (float)(t + 1);
    const float* hrow = H + (long)m * NPROJ;
    const float* co = cs + ((long)b * NCH + ch) * SCANC;
    const float cb = hrow[512 + r]  + co[r];
    const float ct = hrow[768 + r]  + co[256 + r];
    const float z  = (hrow[1024 + r] + co[512 + r]) * inv;
    const float gb = hrow[r] * cb * inv;
    const float gt = alpha[0] * hrow[256 + r] * z * ct * inv;
    const long o = (long)m * R2 + r;
    __nv_bfloat16 h, l;
    bf_split(gb, h, l); Gh[o] = h;        Gl[o] = l;
    bf_split(gt, h, l); Gh[o + RANK] = h; Gl[o + RANK] = l;
}

// bo[d] = sum_e Wo[d,e] * (bias_b[e] + alpha*bias_t[e])
__global__ void bo_kernel(const float* __restrict__ Wo, const float* __restrict__ bb,
                          const float* __restrict__ bt, const float* __restrict__ alpha,
                          float* __restrict__ bo)
{
    const int w = (blockIdx.x * blockDim.x + threadIdx.x) >> 5;
    const int lane = threadIdx.x & 31;
    if (w >= D_MODEL) return;
    const float a = alpha[0];
    float s = 0.f;
    for (int e = lane; e < D_MODEL; e += 32)
        s += Wo[(long)w * D_MODEL + e] * (bb[e] + a * bt[e]);
#pragma unroll
    for (int o = 16; o; o >>= 1) s += __shfl_xor_sync(0xFFFFFFFFu, s, o);
    if (lane == 0) bo[w] = s;
}

// ---------------- launch ------------------------------------------------------
extern "C" void kernel_launch(void* const* d_in, const int* in_sizes, int n_in,
                              void* d_out, int out_size)
{
    const float* x      = (const float*)d_in[0];
    const float* Wq     = (const float*)d_in[1];
    const float* Wk     = (const float*)d_in[2];
    const float* Wo     = (const float*)d_in[3];
    const float* U_b    = (const float*)d_in[4];
    const float* V_b    = (const float*)d_in[5];
    const float* W_b    = (const float*)d_in[6];
    const float* bias_b = (const float*)d_in[7];
    const float* U_t    = (const float*)d_in[8];
    const float* V_t    = (const float*)d_in[9];
    const float* W_t    = (const float*)d_in[10];
    const float* X_t    = (const float*)d_in[11];
    const float* bias_t = (const float*)d_in[12];
    const float* alpha  = (const float*)d_in[13];
    float* out = (float*)d_out;

    float *H, *WqT, *WkT, *VcT, *WcT, *UcT, *bo, *cs;
    __nv_bfloat16 *xh, *xl, *Gh, *Gl, *Bph, *Bpl, *UWoh, *UWol;
    cudaGetSymbolAddress((void**)&H,    g_H);
    cudaGetSymbolAddress((void**)&xh,   g_xh);
    cudaGetSymbolAddress((void**)&xl,   g_xl);
    cudaGetSymbolAddress((void**)&Gh,   g_Gh);
    cudaGetSymbolAddress((void**)&Gl,   g_Gl);
    cudaGetSymbolAddress((void**)&Bph,  g_Bph);
    cudaGetSymbolAddress((void**)&Bpl,  g_Bpl);
    cudaGetSymbolAddress((void**)&UWoh, g_UWoh);
    cudaGetSymbolAddress((void**)&UWol, g_UWol);
    cudaGetSymbolAddress((void**)&WqT,  g_WqT);
    cudaGetSymbolAddress((void**)&WkT,  g_WkT);
    cudaGetSymbolAddress((void**)&VcT,  g_VcT);
    cudaGetSymbolAddress((void**)&WcT,  g_WcT);
    cudaGetSymbolAddress((void**)&UcT,  g_UcT);
    cudaGetSymbolAddress((void**)&bo,   g_bo);
    cudaGetSymbolAddress((void**)&cs,   g_cs);

    cudaFuncSetAttribute(gemm_pre<false>, cudaFuncAttributeMaxDynamicSharedMemorySize, PRE_SMEM);
    cudaFuncSetAttribute(gemm_pre<true>,  cudaFuncAttributeMaxDynamicSharedMemorySize, PRE_SMEM);
    cudaFuncSetAttribute(gemm_prep,       cudaFuncAttributeMaxDynamicSharedMemorySize, PREP_SMEM);

    // ---- prep: transposes/concats + bias fold + x split ----
    dim3 tgrid(32, 32, 9), tblk(32, 8);
    trans_batched<<<tgrid, tblk>>>(Wq, Wk, V_b, V_t, W_b, W_t, U_b, U_t, X_t,
                                   WqT, WkT, VcT, WcT, UcT, Bph, Bpl);
    bo_kernel<<<128, 256>>>(Wo, bias_b, bias_t, alpha, bo);
    split_x<<<4096, 256>>>(x, xh, xl);

    // ---- batched prep GEMMs (one wave of 96 live CTAs) ----
    dim3 gprep(8, 8, 3);
    gemm_prep<<<gprep, 256, PREP_SMEM>>>(VcT, WqT, WcT, WkT, Wo, UcT,
                                         Bph, Bpl, UWoh, UWol);

    // ---- main: H = x @ Bp^T  [8192, 1280] ----
    dim3 gH(NPROJ / 128, MTOT / 128);
    gemm_pre<false><<<gH, 256, PRE_SMEM>>>(xh, xl, Bph, Bpl, H, NPROJ, D_MODEL, nullptr);

    // ---- causal scan over H cols [512,1280) ----
    dim3 gs(SCANC / 128, NCH, BATCH);
    scan_partial<<<gs, 128>>>(H + 512, cs);
    scan_offsets<<<(BATCH * SCANC + 255) / 256, 256>>>(cs);

    // ---- fused apply + build G (bf16 split) ----
    apply_build<<<(MTOT * RANK + 255) / 256, 256>>>(H, cs, alpha, Gh, Gl);

    // ---- out = G @ UWo^T + bo  [8192, 1024] ----
    dim3 gO(D_MODEL / 128, MTOT / 128);
    gemm_pre<true><<<gO, 256, PRE_SMEM>>>(Gh, Gl, UWoh, UWol, out, D_MODEL, R2, bo);
}

// round 6
// speedup vs baseline: 5.7786x; 1.0343x over previous
#include <cuda_runtime.h>
#include <cuda_bf16.h>
#include <cstdint>

// Problem constants (fixed shapes)
#define D_MODEL 1024
#define RANK    256
#define R2      (2*RANK)          // 512
#define NPROJ   (R2 + R2 + RANK)  // 1280 = [a_b|a_t | c_b|c_t | z]
#define BATCH   4
#define SEQ     2048
#define MTOT    (BATCH*SEQ)       // 8192
#define TCH     128
#define NCH     (SEQ/TCH)         // 16
#define SCANC   (R2 + RANK)       // 768 scanned columns
#define PHALF   (1024*1024 + 1024*512)   // prep partial size (floats)

// ---------------- scratch (device globals; no cudaMalloc allowed) ------------
__device__ float         g_H   [MTOT*NPROJ];   // also reused as prep partial scratch
__device__ __nv_bfloat16 g_xh  [MTOT*D_MODEL];
__device__ __nv_bfloat16 g_xl  [MTOT*D_MODEL];
__device__ __nv_bfloat16 g_Gh  [MTOT*R2];
__device__ __nv_bfloat16 g_Gl  [MTOT*R2];
__device__ __nv_bfloat16 g_Bph [NPROJ*D_MODEL];
__device__ __nv_bfloat16 g_Bpl [NPROJ*D_MODEL];
__device__ __nv_bfloat16 g_UWoh[D_MODEL*R2];
__device__ __nv_bfloat16 g_UWol[D_MODEL*R2];
__device__ float g_WqT[D_MODEL*D_MODEL];
__device__ float g_WkT[D_MODEL*D_MODEL];
__device__ float g_VcT[R2*D_MODEL];
__device__ float g_WcT[R2*D_MODEL];
__device__ float g_UcT[R2*D_MODEL];
__device__ float g_bo [D_MODEL];
__device__ float g_cs [BATCH*NCH*SCANC];

// ====================== helpers ==============================================
#define LDSM_X4(R, A) \
    asm volatile("ldmatrix.sync.aligned.m8n8.x4.shared.b16 {%0,%1,%2,%3}, [%4];" \
        : "=r"((R)[0]), "=r"((R)[1]), "=r"((R)[2]), "=r"((R)[3]) : "r"(A))
#define LDSM_X2(R, A) \
    asm volatile("ldmatrix.sync.aligned.m8n8.x2.shared.b16 {%0,%1}, [%2];" \
        : "=r"((R)[0]), "=r"((R)[1]) : "r"(A))
#define MMA_BF16(D, Ar, Br) \
    asm volatile("mma.sync.aligned.m16n8k16.row.col.f32.bf16.bf16.f32 " \
        "{%0,%1,%2,%3}, {%4,%5,%6,%7}, {%8,%9}, {%0,%1,%2,%3};" \
        : "+f"((D)[0]), "+f"((D)[1]), "+f"((D)[2]), "+f"((D)[3]) \
        : "r"((Ar)[0]), "r"((Ar)[1]), "r"((Ar)[2]), "r"((Ar)[3]), \
          "r"((Br)[0]), "r"((Br)[1]))

__device__ __forceinline__ uint32_t smem_u32(const void* p) {
    uint32_t a;
    asm("{ .reg .u64 t; cvta.to.shared.u64 t, %1; cvt.u32.u64 %0, t; }" : "=r"(a) : "l"(p));
    return a;
}

// paired-row swizzled byte offset for element chunk (m in [0,128), c in [0,4))
__device__ __forceinline__ uint32_t swoff(int m, int c) {
    const int p  = m >> 1;
    const int cc = (((m & 1) << 2) | c) ^ (p & 7);
    return (uint32_t)(p * 128 + cc * 16);
}

__device__ __forceinline__ uint32_t pack2(__nv_bfloat16 x, __nv_bfloat16 y) {
    return (uint32_t)__bfloat16_as_ushort(x) | ((uint32_t)__bfloat16_as_ushort(y) << 16);
}

__device__ __forceinline__ void bf_split(float v, __nv_bfloat16& h, __nv_bfloat16& l) {
    h = __float2bfloat16(v);
    l = __float2bfloat16(v - __bfloat162float(h));
}

__device__ __forceinline__ void cpasync16(uint32_t dst, const void* src) {
    asm volatile("cp.async.cg.shared.global [%0], [%1], 16;" :: "r"(dst), "l"(src));
}
#define CP_COMMIT() asm volatile("cp.async.commit_group;" ::: "memory")
#define CP_WAIT1()  asm volatile("cp.async.wait_group 1;"  ::: "memory")

__device__ __forceinline__ void split_sts(float4 v0, float4 v1, char* hp, char* lp) {
    float s[8] = {v0.x, v0.y, v0.z, v0.w, v1.x, v1.y, v1.z, v1.w};
    __nv_bfloat16 h[8], l[8];
#pragma unroll
    for (int q = 0; q < 8; q++) bf_split(s[q], h[q], l[q]);
    uint4 H, L;
    H.x = pack2(h[0], h[1]); H.y = pack2(h[2], h[3]);
    H.z = pack2(h[4], h[5]); H.w = pack2(h[6], h[7]);
    L.x = pack2(l[0], l[1]); L.y = pack2(l[2], l[3]);
    L.z = pack2(l[4], l[5]); L.w = pack2(l[6], l[7]);
    *(uint4*)hp = H;
    *(uint4*)lp = L;
}

// ====================== pre-split bf16 tensor GEMM (main path) ===============
// C[M,N] = (Ah+Al)[M,K] @ (Bh+Bl)[N,K]^T, 3-term split; 3-stage cp.async,
// 2 CTAs/SM (96 KB smem, <=128 regs).
#define TILE_B     8192
#define STAGE_B    32768
#define PRE_SMEM   (3*STAGE_B)   // 96 KB

template<bool BIAS>
__global__ __launch_bounds__(256, 2)
void gemm_pre(const __nv_bfloat16* __restrict__ Ah_g, const __nv_bfloat16* __restrict__ Al_g,
              const __nv_bfloat16* __restrict__ Bh_g, const __nv_bfloat16* __restrict__ Bl_g,
              float* __restrict__ C, int N, int K, const float* __restrict__ bias)
{
    extern __shared__ __align__(128) char sm[];
    const uint32_t sb = smem_u32(sm);
    const int tid  = threadIdx.x;
    const int wid  = tid >> 5, lane = tid & 31;
    const int warpM = wid & 1, warpN = wid >> 1;
    const long bm = (long)blockIdx.y * 128, bn = (long)blockIdx.x * 128;

    // compact LDSM address bases (affine in i/j blocks: +16 rows => +1024 B)
    uint32_t offA0[2], offB0[2], offB1[2];
#pragma unroll
    for (int kg = 0; kg < 2; kg++) {
        offA0[kg] = swoff(warpM * 64 + (lane & 15),      2 * kg + (lane >> 4));
        offB0[kg] = swoff(warpN * 32 + (lane & 7),       2 * kg + ((lane >> 3) & 1));
        offB1[kg] = swoff(warpN * 32 + 8 + (lane & 7),   2 * kg + ((lane >> 3) & 1));
    }

    const int mrow = tid >> 2, mc = tid & 3;
    const uint32_t so0 = swoff(mrow, mc), so1 = swoff(mrow + 64, mc);

    auto issue = [&](int kt) {
        const uint32_t base = sb + (uint32_t)(kt % 3) * STAGE_B;
        const long koff = (long)kt * 32 + mc * 8;
        const long gA0 = (bm + mrow) * (long)K + koff;
        const long gA1 = gA0 + 64L * K;
        const long gB0 = (bn + mrow) * (long)K + koff;
        const long gB1 = gB0 + 64L * K;
        cpasync16(base + so0,            Ah_g + gA0);
        cpasync16(base + so1,            Ah_g + gA1);
        cpasync16(base + TILE_B + so0,   Al_g + gA0);
        cpasync16(base + TILE_B + so1,   Al_g + gA1);
        cpasync16(base + 2*TILE_B + so0, Bh_g + gB0);
        cpasync16(base + 2*TILE_B + so1, Bh_g + gB1);
        cpasync16(base + 3*TILE_B + so0, Bl_g + gB0);
        cpasync16(base + 3*TILE_B + so1, Bl_g + gB1);
    };

    float acc[4][4][4];
#pragma unroll
    for (int i = 0; i < 4; i++)
#pragma unroll
        for (int j = 0; j < 4; j++)
#pragma unroll
            for (int q = 0; q < 4; q++) acc[i][j][q] = 0.f;

    const int nk = K / 32;   // >= 16
    issue(0); CP_COMMIT();
    issue(1); CP_COMMIT();

#pragma unroll 1
    for (int kt = 0; kt < nk; kt++) {
        CP_WAIT1();
        __syncthreads();
        if (kt + 2 < nk) issue(kt + 2);
        CP_COMMIT();

        const uint32_t bb = sb + (uint32_t)(kt % 3) * STAGE_B;
#pragma unroll
        for (int kg = 0; kg < 2; kg++) {
            uint32_t bh[4][2], bl[4][2];
            LDSM_X2(bh[0], bb + 2*TILE_B + offB0[kg]);
            LDSM_X2(bh[1], bb + 2*TILE_B + offB1[kg]);
            LDSM_X2(bh[2], bb + 2*TILE_B + offB0[kg] + 1024);
            LDSM_X2(bh[3], bb + 2*TILE_B + offB1[kg] + 1024);
            LDSM_X2(bl[0], bb + 3*TILE_B + offB0[kg]);
            LDSM_X2(bl[1], bb + 3*TILE_B + offB1[kg]);
            LDSM_X2(bl[2], bb + 3*TILE_B + offB0[kg] + 1024);
            LDSM_X2(bl[3], bb + 3*TILE_B + offB1[kg] + 1024);
#pragma unroll
            for (int i = 0; i < 4; i++) {
                uint32_t ah[4], al[4];
                const uint32_t ao = bb + offA0[kg] + (uint32_t)i * 1024;
                LDSM_X4(ah, ao);
                LDSM_X4(al, ao + TILE_B);
#pragma unroll
                for (int j = 0; j < 4; j++) {
                    MMA_BF16(acc[i][j], ah, bh[j]);
                    MMA_BF16(acc[i][j], ah, bl[j]);
                    MMA_BF16(acc[i][j], al, bh[j]);
                }
            }
        }
    }

    const int g = lane >> 2, tg = lane & 3;
#pragma unroll
    for (int i = 0; i < 4; i++) {
        const long row = bm + warpM * 64 + i * 16 + g;
#pragma unroll
        for (int j = 0; j < 4; j++) {
            const int col = (int)bn + warpN * 32 + j * 8 + 2 * tg;
            float b0 = 0.f, b1 = 0.f;
            if (BIAS) { b0 = bias[col]; b1 = bias[col + 1]; }
            float2 v0 = make_float2(acc[i][j][0] + b0, acc[i][j][1] + b1);
            float2 v1 = make_float2(acc[i][j][2] + b0, acc[i][j][3] + b1);
            *(float2*)(C + row * N + col)       = v0;
            *(float2*)(C + (row + 8) * N + col) = v1;
        }
    }
}

// ====================== fp32-input prep GEMM (split-K x2, fp32 partials) =====
// id=0: P[0..512x1024)       = VcT @ WqT^T
// id=1: P[512x1024..1Mx)     = WcT @ WkT^T
// id=2: P[1M..1.5M)          = Wo @ UcT^T   (1024x512)
// half = z/3 selects K-half; partial -> P + half*PHALF.
#define BUF_B    32768
#define PREP_SMEM 65536

__global__ __launch_bounds__(256, 1)
void gemm_prep(const float* __restrict__ VcT, const float* __restrict__ WqT,
               const float* __restrict__ WcT, const float* __restrict__ WkT,
               const float* __restrict__ Wo,  const float* __restrict__ UcT,
               float* __restrict__ P)
{
    const int id = blockIdx.z % 3, half = blockIdx.z / 3;
    const float *A, *B;
    int Mt, Nt, ldc; long ooff;
    if (id == 0)      { A = VcT; B = WqT; Mt = 512;  Nt = 1024; ldc = 1024; ooff = 0; }
    else if (id == 1) { A = WcT; B = WkT; Mt = 512;  Nt = 1024; ldc = 1024; ooff = 512L*1024; }
    else              { A = Wo;  B = UcT; Mt = 1024; Nt = 512;  ldc = 512;  ooff = 1024L*1024; }
    if ((int)blockIdx.y * 128 >= Mt || (int)blockIdx.x * 128 >= Nt) return;
    const int Kfull = 1024, K = 512, N = Nt;
    A += half * 512;  B += half * 512;
    float* Cp = P + (long)half * PHALF + ooff;

    extern __shared__ __align__(128) char sm[];
    const int tid  = threadIdx.x;
    const int wid  = tid >> 5, lane = tid & 31;
    const int warpM = wid & 1, warpN = wid >> 1;
    const long bm = (long)blockIdx.y * 128, bn = (long)blockIdx.x * 128;
    const uint32_t sb = smem_u32(sm);

    uint32_t offA0[2], offB0[2], offB1[2];
#pragma unroll
    for (int kg = 0; kg < 2; kg++) {
        offA0[kg] = swoff(warpM * 64 + (lane & 15),      2 * kg + (lane >> 4));
        offB0[kg] = swoff(warpN * 32 + (lane & 7),       2 * kg + ((lane >> 3) & 1));
        offB1[kg] = swoff(warpN * 32 + 8 + (lane & 7),   2 * kg + ((lane >> 3) & 1));
    }

    const int r0 = tid >> 2, c0 = tid & 3;
    const uint32_t so0 = swoff(r0, c0), so1 = swoff(r0 + 64, c0);
    const float* Ag0 = A + (bm + r0) * Kfull + c0 * 8;
    const float* Ag1 = Ag0 + 64L * Kfull;
    const float* Bg0 = B + (bn + r0) * Kfull + c0 * 8;
    const float* Bg1 = Bg0 + 64L * Kfull;

    float4 pa0, pa1, pa2, pa3, pb0, pb1, pb2, pb3;
    auto ldg = [&](int kt) {
        const long o = (long)kt * 32;
        pa0 = *(const float4*)(Ag0 + o); pa1 = *(const float4*)(Ag0 + o + 4);
        pa2 = *(const float4*)(Ag1 + o); pa3 = *(const float4*)(Ag1 + o + 4);
        pb0 = *(const float4*)(Bg0 + o); pb1 = *(const float4*)(Bg0 + o + 4);
        pb2 = *(const float4*)(Bg1 + o); pb3 = *(const float4*)(Bg1 + o + 4);
    };
    auto sts = [&](int buf) {
        char* base = sm + buf * BUF_B;
        split_sts(pa0, pa1, base + so0,            base + TILE_B + so0);
        split_sts(pa2, pa3, base + so1,            base + TILE_B + so1);
        split_sts(pb0, pb1, base + 2*TILE_B + so0, base + 3*TILE_B + so0);
        split_sts(pb2, pb3, base + 2*TILE_B + so1, base + 3*TILE_B + so1);
    };

    float acc[4][4][4];
#pragma unroll
    for (int i = 0; i < 4; i++)
#pragma unroll
        for (int j = 0; j < 4; j++)
#pragma unroll
            for (int q = 0; q < 4; q++) acc[i][j][q] = 0.f;

    const int nk = K / 32;
    ldg(0);
    sts(0);
    __syncthreads();

#pragma unroll 1
    for (int kt = 0; kt < nk; kt++) {
        const bool pref = (kt + 1 < nk);
        if (pref) ldg(kt + 1);
        const uint32_t bb = sb + (kt & 1) * BUF_B;
#pragma unroll
        for (int kg = 0; kg < 2; kg++) {
            uint32_t bh[4][2], bl[4][2];
            LDSM_X2(bh[0], bb + 2*TILE_B + offB0[kg]);
            LDSM_X2(bh[1], bb + 2*TILE_B + offB1[kg]);
            LDSM_X2(bh[2], bb + 2*TILE_B + offB0[kg] + 1024);
            LDSM_X2(bh[3], bb + 2*TILE_B + offB1[kg] + 1024);
            LDSM_X2(bl[0], bb + 3*TILE_B + offB0[kg]);
            LDSM_X2(bl[1], bb + 3*TILE_B + offB1[kg]);
            LDSM_X2(bl[2], bb + 3*TILE_B + offB0[kg] + 1024);
            LDSM_X2(bl[3], bb + 3*TILE_B + offB1[kg] + 1024);
#pragma unroll
            for (int i = 0; i < 4; i++) {
                uint32_t ah[4], al[4];
                const uint32_t ao = bb + offA0[kg] + (uint32_t)i * 1024;
                LDSM_X4(ah, ao);
                LDSM_X4(al, ao + TILE_B);
#pragma unroll
                for (int j = 0; j < 4; j++) {
                    MMA_BF16(acc[i][j], ah, bh[j]);
                    MMA_BF16(acc[i][j], ah, bl[j]);
                    MMA_BF16(acc[i][j], al, bh[j]);
                }
            }
        }
        if (pref) sts((kt + 1) & 1);
        __syncthreads();
    }

    const int g = lane >> 2, tg = lane & 3;
#pragma unroll
    for (int i = 0; i < 4; i++) {
        const long row = bm + warpM * 64 + i * 16 + g;
#pragma unroll
        for (int j = 0; j < 4; j++) {
            const int col = (int)bn + warpN * 32 + j * 8 + 2 * tg;
            *(float2*)(Cp + row * ldc + col)       = make_float2(acc[i][j][0], acc[i][j][1]);
            *(float2*)(Cp + (row + 8) * ldc + col) = make_float2(acc[i][j][2], acc[i][j][3]);
        }
    }
}

// combine split-K halves, split to bf16 hi/lo planes
__global__ void combine_prep(const float* __restrict__ P,
                             __nv_bfloat16* __restrict__ Bph, __nv_bfloat16* __restrict__ Bpl,
                             __nv_bfloat16* __restrict__ UWoh, __nv_bfloat16* __restrict__ UWol)
{
    const long n = PHALF;
    for (long i = (long)blockIdx.x * blockDim.x + threadIdx.x; i < n;
         i += (long)gridDim.x * blockDim.x) {
        const float v = P[i] + P[PHALF + i];
        __nv_bfloat16 h, l;
        bf_split(v, h, l);
        if (i < 1024L * 1024) { Bph[i] = h; Bpl[i] = l; }
        else { UWoh[i - 1024L*1024] = h; UWol[i - 1024L*1024] = l; }
    }
}

// ====================== batched tiled transpose / concat =====================
__global__ void trans_batched(const float* __restrict__ Wq, const float* __restrict__ Wk,
                              const float* __restrict__ V_b, const float* __restrict__ V_t,
                              const float* __restrict__ W_b, const float* __restrict__ W_t,
                              const float* __restrict__ U_b, const float* __restrict__ U_t,
                              const float* __restrict__ X_t,
                              float* __restrict__ WqT, float* __restrict__ WkT,
                              float* __restrict__ VcT, float* __restrict__ WcT,
                              float* __restrict__ UcT,
                              __nv_bfloat16* __restrict__ Bph, __nv_bfloat16* __restrict__ Bpl)
{
    __shared__ float t[32][33];
    const int z = blockIdx.z;
    const float* src; int Cin; float* dst = nullptr; int roff = 0; bool split = false;
    switch (z) {
        case 0: src = Wq;  Cin = 1024; dst = WqT; break;
        case 1: src = Wk;  Cin = 1024; dst = WkT; break;
        case 2: src = V_b; Cin = 256;  dst = VcT; roff = 0;    break;
        case 3: src = V_t; Cin = 256;  dst = VcT; roff = 256;  break;
        case 4: src = W_b; Cin = 256;  dst = WcT; roff = 0;    break;
        case 5: src = W_t; Cin = 256;  dst = WcT; roff = 256;  break;
        case 6: src = U_b; Cin = 256;  dst = UcT; roff = 0;    break;
        case 7: src = U_t; Cin = 256;  dst = UcT; roff = 256;  break;
        default: src = X_t; Cin = 256; split = true; roff = 1024; break;
    }
    const int bx = blockIdx.x, by = blockIdx.y;
    if (Cin == 256 && bx >= 8) return;
    const int tx = threadIdx.x, ty = threadIdx.y;
#pragma unroll
    for (int j = 0; j < 32; j += 8)
        t[ty + j][tx] = src[(long)(by * 32 + ty + j) * Cin + bx * 32 + tx];
    __syncthreads();
    if (!split) {
#pragma unroll
        for (int j = 0; j < 32; j += 8)
            dst[(long)(roff + bx * 32 + ty + j) * 1024 + by * 32 + tx] = t[tx][ty + j];
    } else {
#pragma unroll
        for (int j = 0; j < 32; j += 8) {
            __nv_bfloat16 h, l;
            bf_split(t[tx][ty + j], h, l);
            const long o = (long)(roff + bx * 32 + ty + j) * 1024 + by * 32 + tx;
            Bph[o] = h; Bpl[o] = l;
        }
    }
}

// ---------------- split x into bf16 hi/lo planes -----------------------------
__global__ void split_x(const float* __restrict__ x,
                        __nv_bfloat16* __restrict__ xh, __nv_bfloat16* __restrict__ xl)
{
    const long n4 = (long)MTOT * D_MODEL / 4;
    for (long i = (long)blockIdx.x * blockDim.x + threadIdx.x; i < n4;
         i += (long)gridDim.x * blockDim.x) {
        float4 v = ((const float4*)x)[i];
        __nv_bfloat16 h[4], l[4];
        bf_split(v.x, h[0], l[0]); bf_split(v.y, h[1], l[1]);
        bf_split(v.z, h[2], l[2]); bf_split(v.w, h[3], l[3]);
        uint2 H, L;
        H.x = pack2(h[0], h[1]); H.y = pack2(h[2], h[3]);
        L.x = pack2(l[0], l[1]); L.y = pack2(l[2], l[3]);
        ((uint2*)xh)[i] = H;
        ((uint2*)xl)[i] = L;
    }
}

// ---------------- causal cumulative scan (cols 512..1280 of H) --------------
__global__ void scan_partial(float* __restrict__ Hc, float* __restrict__ cs)
{
    const int col = blockIdx.x * 128 + threadIdx.x;   // 0..767
    const int ch  = blockIdx.y;
    const int b   = blockIdx.z;
    const long base = ((long)b * SEQ + (long)ch * TCH) * NPROJ + col;
    float run = 0.f;
    for (int t = 0; t < TCH; t++) {
        run += Hc[base + (long)t * NPROJ];
        Hc[base + (long)t * NPROJ] = run;
    }
    cs[((long)b * NCH + ch) * SCANC + col] = run;
}

__global__ void scan_offsets(float* __restrict__ cs)
{
    const int i = blockIdx.x * blockDim.x + threadIdx.x;
    if (i >= BATCH * SCANC) return;
    const int b = i / SCANC, col = i % SCANC;
    float off = 0.f;
    for (int ch = 0; ch < NCH; ch++) {
        const long idx = ((long)b * NCH + ch) * SCANC + col;
        const float v = cs[idx];
        cs[idx] = off;
        off += v;
    }
}

// ---------------- fused scan-apply + G build (bf16 split output) -------------
__global__ void apply_build(const float* __restrict__ H, const float* __restrict__ cs,
                            const float* __restrict__ alpha,
                            __nv_bfloat16* __restrict__ Gh, __nv_bfloat16* __restrict__ Gl)
{
    const int i = blockIdx.x * blockDim.x + threadIdx.x;
    if (i >= MTOT * RANK) return;
    const int m = i / RANK, r = i % RANK;
    const int t = m % SEQ, b = m / SEQ, ch = t / TCH;
    const float inv = 1.0f / (float)(t + 1);
    const float* hrow = H + (long)m * NPROJ;
    const float* co = cs + ((long)b * NCH + ch) * SCANC;
    const float cb = hrow[512 + r]  + co[r];
    const float ct = hrow[768 + r]  + co[256 + r];
    const float z  = (hrow[1024 + r] + co[512 + r]) * inv;
    const float gb = hrow[r] * cb * inv;
    const float gt = alpha[0] * hrow[256 + r] * z * ct * inv;
    const long o = (long)m * R2 + r;
    __nv_bfloat16 h, l;
    bf_split(gb, h, l); Gh[o] = h;        Gl[o] = l;
    bf_split(gt, h, l); Gh[o + RANK] = h; Gl[o + RANK] = l;
}

// bo[d] = sum_e Wo[d,e] * (bias_b[e] + alpha*bias_t[e])
__global__ void bo_kernel(const float* __restrict__ Wo, const float* __restrict__ bb,
                          const float* __restrict__ bt, const float* __restrict__ alpha,
                          float* __restrict__ bo)
{
    const int w = (blockIdx.x * blockDim.x + threadIdx.x) >> 5;
    const int lane = threadIdx.x & 31;
    if (w >= D_MODEL) return;
    const float a = alpha[0];
    float s = 0.f;
    for (int e = lane; e < D_MODEL; e += 32)
        s += Wo[(long)w * D_MODEL + e] * (bb[e] + a * bt[e]);
#pragma unroll
    for (int o = 16; o; o >>= 1) s += __shfl_xor_sync(0xFFFFFFFFu, s, o);
    if (lane == 0) bo[w] = s;
}

// ---------------- launch ------------------------------------------------------
extern "C" void kernel_launch(void* const* d_in, const int* in_sizes, int n_in,
                              void* d_out, int out_size)
{
    const float* x      = (const float*)d_in[0];
    const float* Wq     = (const float*)d_in[1];
    const float* Wk     = (const float*)d_in[2];
    const float* Wo     = (const float*)d_in[3];
    const float* U_b    = (const float*)d_in[4];
    const float* V_b    = (const float*)d_in[5];
    const float* W_b    = (const float*)d_in[6];
    const float* bias_b = (const float*)d_in[7];
    const float* U_t    = (const float*)d_in[8];
    const float* V_t    = (const float*)d_in[9];
    const float* W_t    = (const float*)d_in[10];
    const float* X_t    = (const float*)d_in[11];
    const float* bias_t = (const float*)d_in[12];
    const float* alpha  = (const float*)d_in[13];
    float* out = (float*)d_out;

    float *H, *WqT, *WkT, *VcT, *WcT, *UcT, *bo, *cs;
    __nv_bfloat16 *xh, *xl, *Gh, *Gl, *Bph, *Bpl, *UWoh, *UWol;
    cudaGetSymbolAddress((void**)&H,    g_H);
    cudaGetSymbolAddress((void**)&xh,   g_xh);
    cudaGetSymbolAddress((void**)&xl,   g_xl);
    cudaGetSymbolAddress((void**)&Gh,   g_Gh);
    cudaGetSymbolAddress((void**)&Gl,   g_Gl);
    cudaGetSymbolAddress((void**)&Bph,  g_Bph);
    cudaGetSymbolAddress((void**)&Bpl,  g_Bpl);
    cudaGetSymbolAddress((void**)&UWoh, g_UWoh);
    cudaGetSymbolAddress((void**)&UWol, g_UWol);
    cudaGetSymbolAddress((void**)&WqT,  g_WqT);
    cudaGetSymbolAddress((void**)&WkT,  g_WkT);
    cudaGetSymbolAddress((void**)&VcT,  g_VcT);
    cudaGetSymbolAddress((void**)&WcT,  g_WcT);
    cudaGetSymbolAddress((void**)&UcT,  g_UcT);
    cudaGetSymbolAddress((void**)&bo,   g_bo);
    cudaGetSymbolAddress((void**)&cs,   g_cs);

    cudaFuncSetAttribute(gemm_pre<false>, cudaFuncAttributeMaxDynamicSharedMemorySize, PRE_SMEM);
    cudaFuncSetAttribute(gemm_pre<true>,  cudaFuncAttributeMaxDynamicSharedMemorySize, PRE_SMEM);
    cudaFuncSetAttribute(gemm_prep,       cudaFuncAttributeMaxDynamicSharedMemorySize, PREP_SMEM);

    // ---- prep: transposes/concats + bias fold + x split ----
    dim3 tgrid(32, 32, 9), tblk(32, 8);
    trans_batched<<<tgrid, tblk>>>(Wq, Wk, V_b, V_t, W_b, W_t, U_b, U_t, X_t,
                                   WqT, WkT, VcT, WcT, UcT, Bph, Bpl);
    bo_kernel<<<128, 256>>>(Wo, bias_b, bias_t, alpha, bo);
    split_x<<<4096, 256>>>(x, xh, xl);

    // ---- split-K prep GEMMs (192 active CTAs) + combine ----
    dim3 gprep(8, 8, 6);
    gemm_prep<<<gprep, 256, PREP_SMEM>>>(VcT, WqT, WcT, WkT, Wo, UcT, H);
    combine_prep<<<1536, 256>>>(H, Bph, Bpl, UWoh, UWol);

    // ---- main: H = x @ Bp^T  [8192, 1280] ----
    dim3 gH(NPROJ / 128, MTOT / 128);
    gemm_pre<false><<<gH, 256, PRE_SMEM>>>(xh, xl, Bph, Bpl, H, NPROJ, D_MODEL, nullptr);

    // ---- causal scan over H cols [512,1280) ----
    dim3 gs(SCANC / 128, NCH, BATCH);
    scan_partial<<<gs, 128>>>(H + 512, cs);
    scan_offsets<<<(BATCH * SCANC + 255) / 256, 256>>>(cs);

    // ---- fused apply + build G (bf16 split) ----
    apply_build<<<(MTOT * RANK + 255) / 256, 256>>>(H, cs, alpha, Gh, Gl);

    // ---- out = G @ UWo^T + bo  [8192, 1024] ----
    dim3 gO(D_MODEL / 128, MTOT / 128);
    gemm_pre<true><<<gO, 256, PRE_SMEM>>>(Gh, Gl, UWoh, UWol, out, D_MODEL, R2, bo);
}